// round 6
// baseline (speedup 1.0000x reference)
#include <cuda_runtime.h>
#include <cuda_bf16.h>
#include <cstdint>

// ===========================================================================
// WeightPopupLayer: out = x @ (W * topk_mask(|scores|, 50%)).T + bias
// Round 6: two-level int8 quantization (v ~ u*(128*vh + vl)), 3-term
// s8 mma.sync (m16n8k32) with exact s32 accumulation (hh in acc1, hl+lh
// share acc2), cp.async.bulk-fed 8-stage ring, blocked pre-swizzled scratch.
// ===========================================================================

#define NTOT   (4096 * 4096)
#define JRANK  8388608u
#define EQ_CAP (1 << 20)

#define M_DIM 8192
#define N_DIM 4096
#define K_DIM 4096

// Blocked int8 scratch: blocks of 128 rows x 32 B (one k32 chunk) = 4096 B.
// A: [tile=64][ks=128] blocks; B: [tile=32][ks=128] blocks.
// In-block: off = rl*32 + ((c ^ ((rl>>2)&1)) << 4) + (k&15)   (c = (k>>4)&1)
__device__ __align__(16) signed char g_ah[M_DIM * K_DIM];   // 32 MB
__device__ __align__(16) signed char g_al[M_DIM * K_DIM];   // 32 MB
__device__ __align__(16) signed char g_bh[N_DIM * K_DIM];   // 16 MB
__device__ __align__(16) signed char g_bl[N_DIM * K_DIM];   // 16 MB

__device__ unsigned g_hist[256];
__device__ unsigned g_prefix;
__device__ unsigned g_rank;
__device__ unsigned g_neq;
__device__ unsigned g_idxcut;
__device__ unsigned g_eqidx[EQ_CAP];
__device__ unsigned g_maxx, g_maxw;
__device__ float g_ix128, g_ix, g_x128u;   // x quant consts
__device__ float g_iw128, g_iw, g_w128u;   // w quant consts
__device__ float g_s1, g_s2;               // epilogue scales

static __device__ __forceinline__ unsigned abs_bits(float v) {
    return __float_as_uint(fabsf(v));
}

// ======================= init + maxabs =====================================
__global__ void k_init() {
    int t = threadIdx.x;
    if (t < 256) g_hist[t] = 0;
    if (t == 0) {
        g_prefix = 0u; g_rank = JRANK; g_neq = 0u; g_idxcut = 0u;
        g_maxx = 0u; g_maxw = 0u;
    }
}

__global__ void k_max(const float4* __restrict__ p, int n4, int which) {
    __shared__ unsigned sm_[8];
    unsigned m = 0;
    int stride = blockDim.x * gridDim.x;
    for (int i = blockIdx.x * blockDim.x + threadIdx.x; i < n4; i += stride) {
        float4 v = p[i];
        m = max(m, abs_bits(v.x)); m = max(m, abs_bits(v.y));
        m = max(m, abs_bits(v.z)); m = max(m, abs_bits(v.w));
    }
    #pragma unroll
    for (int o = 16; o > 0; o >>= 1) m = max(m, __shfl_xor_sync(0xFFFFFFFFu, m, o));
    int wid = threadIdx.x >> 5;
    if ((threadIdx.x & 31) == 0) sm_[wid] = m;
    __syncthreads();
    if (threadIdx.x == 0) {
        unsigned mm = sm_[0];
        #pragma unroll
        for (int i = 1; i < 8; ++i) mm = max(mm, sm_[i]);
        atomicMax(which ? &g_maxw : &g_maxx, mm);
    }
}

__global__ void k_scales() {
    float mx = __uint_as_float(g_maxx); if (!(mx > 0.0f)) mx = 1.0f;
    float mw = __uint_as_float(g_maxw); if (!(mw > 0.0f)) mw = 1.0f;
    float ux = mx / 16256.0f, uw = mw / 16256.0f;
    g_ix128 = 1.0f / (128.0f * ux); g_ix = 1.0f / ux; g_x128u = 128.0f * ux;
    g_iw128 = 1.0f / (128.0f * uw); g_iw = 1.0f / uw; g_w128u = 128.0f * uw;
    g_s1 = 16384.0f * ux * uw;
    g_s2 = 128.0f * ux * uw;
}

// ======================= selection kernels =================================
__global__ void k_hist(const float4* __restrict__ s4, int n4, int shift) {
    __shared__ unsigned sh[256];
    if (threadIdx.x < 256) sh[threadIdx.x] = 0;
    __syncthreads();
    const unsigned pref = g_prefix;
    const unsigned mask = (shift == 24) ? 0u : (0xFFFFFFFFu << (shift + 8));
    int stride = blockDim.x * gridDim.x;
    for (int i = blockIdx.x * blockDim.x + threadIdx.x; i < n4; i += stride) {
        float4 v = s4[i];
        unsigned b;
        b = abs_bits(v.x); if ((b & mask) == pref) atomicAdd(&sh[(b >> shift) & 255], 1u);
        b = abs_bits(v.y); if ((b & mask) == pref) atomicAdd(&sh[(b >> shift) & 255], 1u);
        b = abs_bits(v.z); if ((b & mask) == pref) atomicAdd(&sh[(b >> shift) & 255], 1u);
        b = abs_bits(v.w); if ((b & mask) == pref) atomicAdd(&sh[(b >> shift) & 255], 1u);
    }
    __syncthreads();
    if (threadIdx.x < 256 && sh[threadIdx.x])
        atomicAdd(&g_hist[threadIdx.x], sh[threadIdx.x]);
}

__global__ void k_pick(int shift) {
    unsigned r = g_rank, cum = 0;
    #pragma unroll 1
    for (int b = 0; b < 256; ++b) {
        unsigned c = g_hist[b];
        if (cum + c > r) { g_prefix |= ((unsigned)b) << shift; g_rank = r - cum; break; }
        cum += c;
    }
    for (int b = 0; b < 256; ++b) g_hist[b] = 0;
}

__global__ void k_gather(const float4* __restrict__ s4, int n4) {
    const unsigned tb = g_prefix;
    int stride = blockDim.x * gridDim.x;
    for (int i = blockIdx.x * blockDim.x + threadIdx.x; i < n4; i += stride) {
        float4 v = s4[i];
        unsigned base = (unsigned)i << 2;
        if (abs_bits(v.x) == tb) { unsigned p = atomicAdd(&g_neq, 1u); if (p < EQ_CAP) g_eqidx[p] = base + 0; }
        if (abs_bits(v.y) == tb) { unsigned p = atomicAdd(&g_neq, 1u); if (p < EQ_CAP) g_eqidx[p] = base + 1; }
        if (abs_bits(v.z) == tb) { unsigned p = atomicAdd(&g_neq, 1u); if (p < EQ_CAP) g_eqidx[p] = base + 2; }
        if (abs_bits(v.w) == tb) { unsigned p = atomicAdd(&g_neq, 1u); if (p < EQ_CAP) g_eqidx[p] = base + 3; }
    }
}

__global__ void k_select_cut() {
    unsigned m = min(g_neq, (unsigned)EQ_CAP);
    unsigned d = g_rank;
    if (threadIdx.x == 0) {
        if (d == 0u) g_idxcut = 0u;
        else if (d >= m) g_idxcut = 0xFFFFFFFFu;
    }
    if (d == 0u || d >= m) return;
    for (unsigned e = threadIdx.x; e < m; e += blockDim.x) {
        unsigned v = g_eqidx[e];
        unsigned rank = 0;
        for (unsigned f = 0; f < m; ++f) rank += (g_eqidx[f] < v);
        if (rank == d) g_idxcut = v;
    }
}

// ======================= quantization kernels ==============================
static __device__ __forceinline__ void q2(float f, float i128, float iu, float u128,
                                          int& qh, int& ql) {
    int h = __float2int_rn(f * i128);
    h = max(-127, min(127, h));
    float r = fmaf((float)(-h), u128, f);
    int l = __float2int_rn(r * iu);
    l = max(-127, min(127, l));
    qh = h; ql = l;
}

static __device__ __forceinline__ unsigned pack4b(int a, int b, int c, int d) {
    return (unsigned)(a & 255) | ((unsigned)(b & 255) << 8) |
           ((unsigned)(c & 255) << 16) | ((unsigned)(d & 255) << 24);
}

// masked W -> blocked int8 hi/lo
__global__ void k_quant_w(const float4* __restrict__ w4, const float4* __restrict__ s4, int n4) {
    const unsigned tb  = g_prefix;
    const unsigned cut = g_idxcut;
    const float i128 = g_iw128, iu = g_iw, u128 = g_w128u;
    int stride = blockDim.x * gridDim.x;
    for (int i = blockIdx.x * blockDim.x + threadIdx.x; i < n4; i += stride) {
        float4 wv = w4[i], sv = s4[i];
        unsigned fi = (unsigned)i << 2;
        float f[4];
        unsigned b0 = abs_bits(sv.x), b1 = abs_bits(sv.y), b2 = abs_bits(sv.z), b3 = abs_bits(sv.w);
        f[0] = (b0 > tb || (b0 == tb && fi + 0 >= cut)) ? wv.x : 0.0f;
        f[1] = (b1 > tb || (b1 == tb && fi + 1 >= cut)) ? wv.y : 0.0f;
        f[2] = (b2 > tb || (b2 == tb && fi + 2 >= cut)) ? wv.z : 0.0f;
        f[3] = (b3 > tb || (b3 == tb && fi + 3 >= cut)) ? wv.w : 0.0f;
        int h[4], l[4];
        #pragma unroll
        for (int c = 0; c < 4; ++c) q2(f[c], i128, iu, u128, h[c], l[c]);
        unsigned row = fi >> 12, k = fi & 4095;
        unsigned tile = row >> 7, rl = row & 127;
        unsigned ks = k >> 5, c = (k >> 4) & 1, wb = k & 15;
        size_t addr = ((size_t)(tile * 128 + ks) << 12)
                    + rl * 32 + ((c ^ ((rl >> 2) & 1)) << 4) + wb;
        *(unsigned*)(g_bh + addr) = pack4b(h[0], h[1], h[2], h[3]);
        *(unsigned*)(g_bl + addr) = pack4b(l[0], l[1], l[2], l[3]);
    }
}

// x -> blocked int8 hi/lo
__global__ void k_quant_a(const float4* __restrict__ x4, int n4) {
    const float i128 = g_ix128, iu = g_ix, u128 = g_x128u;
    int stride = blockDim.x * gridDim.x;
    for (int i = blockIdx.x * blockDim.x + threadIdx.x; i < n4; i += stride) {
        float4 v = x4[i];
        float f[4] = {v.x, v.y, v.z, v.w};
        int h[4], l[4];
        #pragma unroll
        for (int c = 0; c < 4; ++c) q2(f[c], i128, iu, u128, h[c], l[c]);
        unsigned fi = (unsigned)i << 2;
        unsigned row = fi >> 12, k = fi & 4095;
        unsigned tile = row >> 7, rl = row & 127;
        unsigned ks = k >> 5, c = (k >> 4) & 1, wb = k & 15;
        size_t addr = ((size_t)(tile * 128 + ks) << 12)
                    + rl * 32 + ((c ^ ((rl >> 2) & 1)) << 4) + wb;
        *(unsigned*)(g_ah + addr) = pack4b(h[0], h[1], h[2], h[3]);
        *(unsigned*)(g_al + addr) = pack4b(l[0], l[1], l[2], l[3]);
    }
}

// ======================= int8 GEMM =========================================
// CTA 128x128, 256 threads = 8 warps (2 wm x 4 wn), warp tile 64x32,
// k-step 32. 8-stage ring of 16 KB stages (Ah/Al/Bh/Bl 4 KB each).

#define STAGES   8
#define STB      16384
#define SM_AH    0
#define SM_AL    4096
#define SM_BH    8192
#define SM_BL    12288
#define SMEM_GEMM (STAGES * STB)     // 131072
#define KSTEPS   (K_DIM / 32)        // 128

#define LDSM4(r0, r1, r2, r3, addr) \
    asm volatile("ldmatrix.sync.aligned.m8n8.x4.shared.b16 {%0,%1,%2,%3}, [%4];" \
                 : "=r"(r0), "=r"(r1), "=r"(r2), "=r"(r3) : "r"(addr))

#define MMA_S8(d, a0, a1, a2, a3, b0, b1) \
    asm volatile("mma.sync.aligned.m16n8k32.row.col.s32.s8.s8.s32 " \
                 "{%0,%1,%2,%3}, {%4,%5,%6,%7}, {%8,%9}, {%0,%1,%2,%3};" \
                 : "+r"((d)[0]), "+r"((d)[1]), "+r"((d)[2]), "+r"((d)[3]) \
                 : "r"(a0), "r"(a1), "r"(a2), "r"(a3), "r"(b0), "r"(b1))

#define MBARRIER_INIT(mbar, cnt) \
    asm volatile("mbarrier.init.shared.b64 [%0], %1;" :: "r"((uint32_t)(mbar)), "r"((uint32_t)(cnt)) : "memory")
#define MBARRIER_EXPECT_TX(mbar, tx) \
    asm volatile("mbarrier.arrive.expect_tx.shared.b64 _, [%0], %1;" :: "r"((uint32_t)(mbar)), "r"((uint32_t)(tx)) : "memory")

#define MBARRIER_WAIT_PARITY(mbar_smem_addr, phase_parity) do { \
    uint32_t _mbar = (uint32_t)(mbar_smem_addr); \
    uint32_t _parity = (uint32_t)(phase_parity); \
    uint32_t _done; \
    asm volatile("{\n\t.reg .pred p;\n\t" \
        "mbarrier.try_wait.parity.acquire.cta.shared::cta.b64 p, [%1], %2;\n\t" \
        "selp.b32 %0, 1, 0, p;\n\t}" \
        : "=r"(_done) : "r"(_mbar), "r"(_parity) : "memory"); \
    if (!_done) { \
        asm volatile("{\n\t.reg .pred P1;\n\t" \
            "WAIT_LOOP_%=:\n\t" \
            "mbarrier.try_wait.parity.acquire.cta.shared::cta.b64 P1, [%0], %1, 0x989680;\n\t" \
            "@P1 bra.uni WAIT_DONE_%=;\n\t" \
            "bra.uni WAIT_LOOP_%=;\n\t" \
            "WAIT_DONE_%=:\n\t}" \
            :: "r"(_mbar), "r"(_parity) : "memory"); \
    } \
} while (0)

static __device__ __forceinline__ void bulk_g2s(uint32_t dst, const void* src,
                                                uint32_t bytes, uint32_t mbar) {
    asm volatile(
        "cp.async.bulk.shared::cluster.global.mbarrier::complete_tx::bytes [%0], [%1], %2, [%3];"
        :: "r"(dst), "l"(src), "r"(bytes), "r"(mbar) : "memory");
}

__global__ void __launch_bounds__(256, 1)
k_gemm(const float* __restrict__ bias, float* __restrict__ outp) {
    extern __shared__ __align__(16) char dsmem[];
    __shared__ __align__(8) unsigned long long s_mbar[STAGES];

    uint32_t sb, mb;
    asm("{ .reg .u64 t; cvta.to.shared.u64 t, %1; cvt.u32.u64 %0, t; }" : "=r"(sb) : "l"(dsmem));
    asm("{ .reg .u64 t; cvta.to.shared.u64 t, %1; cvt.u32.u64 %0, t; }" : "=r"(mb) : "l"(&s_mbar[0]));

    const int tid  = threadIdx.x;
    const int wid  = tid >> 5;
    const int lane = tid & 31;

    // raster: consecutive bids sweep all bx for few by -> B resident in L2
    const int bid = blockIdx.x;
    const int bx  = bid & 31;            // N tile (0..31)
    const int by  = bid >> 5;            // M tile (0..63)

    const int wm = wid >> 2;             // 0..1
    const int wn = wid & 3;              // 0..3

    const char* gah = (const char*)g_ah + ((size_t)by << 19);
    const char* gal = (const char*)g_al + ((size_t)by << 19);
    const char* gbh = (const char*)g_bh + ((size_t)bx << 19);
    const char* gbl = (const char*)g_bl + ((size_t)bx << 19);

    // ldmatrix per-lane offsets
    uint32_t offA[4];
    {
        int r0 = wm * 64 + (lane & 7) + ((lane >> 3) & 1) * 8;
        uint32_t ch = (lane >> 4) & 1;
        #pragma unroll
        for (int mt = 0; mt < 4; ++mt) {
            uint32_t R = (uint32_t)(r0 + mt * 16);
            offA[mt] = R * 32 + ((ch ^ ((R >> 2) & 1)) << 4);
        }
    }
    uint32_t offB[2];
    {
        int c0 = wn * 32 + (lane & 7) + ((lane >> 4) & 1) * 8;
        uint32_t ch = (lane >> 3) & 1;
        #pragma unroll
        for (int p = 0; p < 2; ++p) {
            uint32_t C = (uint32_t)(c0 + p * 16);
            offB[p] = C * 32 + ((ch ^ ((C >> 2) & 1)) << 4);
        }
    }

    if (tid == 0) {
        #pragma unroll
        for (int s = 0; s < STAGES; ++s) MBARRIER_INIT(mb + s * 8, 1);
    }
    __syncthreads();

    if (tid == 0) {
        #pragma unroll
        for (int s = 0; s < STAGES - 1; ++s) {
            uint32_t mbar = mb + s * 8;
            uint32_t dst  = sb + s * STB;
            MBARRIER_EXPECT_TX(mbar, STB);
            bulk_g2s(dst + SM_AH, gah + ((size_t)s << 12), 4096, mbar);
            bulk_g2s(dst + SM_AL, gal + ((size_t)s << 12), 4096, mbar);
            bulk_g2s(dst + SM_BH, gbh + ((size_t)s << 12), 4096, mbar);
            bulk_g2s(dst + SM_BL, gbl + ((size_t)s << 12), 4096, mbar);
        }
    }

    int acc1[4][4][4], acc2[4][4][4];
    #pragma unroll
    for (int i = 0; i < 4; ++i)
        #pragma unroll
        for (int j = 0; j < 4; ++j)
            #pragma unroll
            for (int e = 0; e < 4; ++e) { acc1[i][j][e] = 0; acc2[i][j][e] = 0; }

    #pragma unroll 1
    for (int s = 0; s < KSTEPS; ++s) {
        const int slot = s & (STAGES - 1);
        MBARRIER_WAIT_PARITY(mb + slot * 8, (s >> 3) & 1);
        uint32_t sbase = sb + (uint32_t)slot * STB;

        uint32_t ah[4][4], al[4][4], bh[2][4], bl[2][4];
        #pragma unroll
        for (int mt = 0; mt < 4; ++mt) {
            LDSM4(ah[mt][0], ah[mt][1], ah[mt][2], ah[mt][3], sbase + SM_AH + offA[mt]);
            LDSM4(al[mt][0], al[mt][1], al[mt][2], al[mt][3], sbase + SM_AL + offA[mt]);
        }
        #pragma unroll
        for (int p = 0; p < 2; ++p) {
            LDSM4(bh[p][0], bh[p][1], bh[p][2], bh[p][3], sbase + SM_BH + offB[p]);
            LDSM4(bl[p][0], bl[p][1], bl[p][2], bl[p][3], sbase + SM_BL + offB[p]);
        }

        #pragma unroll
        for (int mt = 0; mt < 4; ++mt) {
            #pragma unroll
            for (int p = 0; p < 2; ++p) {
                #pragma unroll
                for (int j = 0; j < 2; ++j) {
                    int nt = 2 * p + j;
                    MMA_S8(acc1[mt][nt], ah[mt][0], ah[mt][1], ah[mt][2], ah[mt][3],
                           bh[p][2 * j], bh[p][2 * j + 1]);
                    MMA_S8(acc2[mt][nt], ah[mt][0], ah[mt][1], ah[mt][2], ah[mt][3],
                           bl[p][2 * j], bl[p][2 * j + 1]);
                    MMA_S8(acc2[mt][nt], al[mt][0], al[mt][1], al[mt][2], al[mt][3],
                           bh[p][2 * j], bh[p][2 * j + 1]);
                }
            }
        }

        __syncthreads();
        if (tid == 0 && s + STAGES - 1 < KSTEPS) {
            const int ns = s + STAGES - 1;
            const int nslot = ns & (STAGES - 1);
            uint32_t mbar = mb + nslot * 8;
            uint32_t dst  = sb + (uint32_t)nslot * STB;
            MBARRIER_EXPECT_TX(mbar, STB);
            bulk_g2s(dst + SM_AH, gah + ((size_t)ns << 12), 4096, mbar);
            bulk_g2s(dst + SM_AL, gal + ((size_t)ns << 12), 4096, mbar);
            bulk_g2s(dst + SM_BH, gbh + ((size_t)ns << 12), 4096, mbar);
            bulk_g2s(dst + SM_BL, gbl + ((size_t)ns << 12), 4096, mbar);
        }
    }

    // ---- epilogue: combine scales, add bias, store fp32 ----
    const float s1 = g_s1, s2 = g_s2;
    #pragma unroll
    for (int p = 0; p < 2; ++p) {
        #pragma unroll
        for (int j = 0; j < 2; ++j) {
            int nt = 2 * p + j;
            int col = bx * 128 + wn * 32 + nt * 8 + (lane & 3) * 2;
            float2 bv = *(const float2*)(bias + col);
            #pragma unroll
            for (int mt = 0; mt < 4; ++mt) {
                int r0 = by * 128 + wm * 64 + mt * 16 + (lane >> 2);
                const int* a1 = acc1[mt][nt];
                const int* a2 = acc2[mt][nt];
                float2 o0, o1;
                o0.x = fmaf(s1, (float)a1[0], fmaf(s2, (float)a2[0], bv.x));
                o0.y = fmaf(s1, (float)a1[1], fmaf(s2, (float)a2[1], bv.y));
                o1.x = fmaf(s1, (float)a1[2], fmaf(s2, (float)a2[2], bv.x));
                o1.y = fmaf(s1, (float)a1[3], fmaf(s2, (float)a2[3], bv.y));
                *(float2*)(outp + (size_t)r0 * N_DIM + col)       = o0;
                *(float2*)(outp + (size_t)(r0 + 8) * N_DIM + col) = o1;
            }
        }
    }
}

// ===========================================================================
extern "C" void kernel_launch(void* const* d_in, const int* in_sizes, int n_in,
                              void* d_out, int out_size) {
    const float* x    = (const float*)d_in[0];
    const float* w    = (const float*)d_in[1];
    const float* bias = (const float*)d_in[2];
    const float* s    = (const float*)d_in[3];
    float* out = (float*)d_out;

    k_init<<<1, 256>>>();
    k_max<<<2048, 256>>>((const float4*)x, (M_DIM * K_DIM) / 4, 0);
    k_max<<<2048, 256>>>((const float4*)w, NTOT / 4, 1);
    for (int shift = 24; shift >= 0; shift -= 8) {
        k_hist<<<1024, 256>>>((const float4*)s, NTOT / 4, shift);
        k_pick<<<1, 1>>>(shift);
    }
    k_gather<<<1024, 256>>>((const float4*)s, NTOT / 4);
    k_select_cut<<<1, 256>>>();
    k_scales<<<1, 1>>>();

    k_quant_w<<<2048, 256>>>((const float4*)w, (const float4*)s, NTOT / 4);
    k_quant_a<<<4096, 256>>>((const float4*)x, (M_DIM * K_DIM) / 4);

    cudaFuncSetAttribute(k_gemm, cudaFuncAttributeMaxDynamicSharedMemorySize, SMEM_GEMM);
    k_gemm<<<2048, 256, SMEM_GEMM>>>(bias, out);
}

// round 7
// speedup vs baseline: 4.7671x; 4.7671x over previous
#include <cuda_runtime.h>
#include <cuda_fp16.h>
#include <cstdint>

// ===========================================================================
// WeightPopupLayer: out = x @ (W * topk_mask(|scores|, 50%)).T + bias
// Round 7: fp16 2-term scheme. A = fp16(x) (residual dropped; rel err
// ~0.29*2^-11 = 1.4e-4). W stored scaled by 2^14 as fp16 hi + fp16 residual
// (both normal range), so W side is ~exact. Both terms chain into one fp32
// accumulator; epilogue scales by 2^-14. 134M HMMA (was 201M with bf16 x3).
// ===========================================================================

#define NTOT   (4096 * 4096)
#define JRANK  8388608u
#define EQ_CAP (1 << 20)

#define M_DIM 8192
#define N_DIM 4096
#define K_DIM 4096

#define WSCALE     16384.0f
#define INV_WSCALE (1.0f / 16384.0f)

// Blocked scratch (fp16):
//   g_ah: [by=32][ks=128] blocks of 256 rows x 64B = 16384 B
//   g_bh/g_bl: [bx=32][ks=128] blocks of 128 rows x 64B = 8192 B
// In-block: off = rl*64 + ((cs ^ ((rl>>1)&3)) << 4) + (kl&7)*2
__device__ __align__(16) __half g_ah[M_DIM * K_DIM];   // 64 MB
__device__ __align__(16) __half g_bh[N_DIM * K_DIM];   // 32 MB
__device__ __align__(16) __half g_bl[N_DIM * K_DIM];   // 32 MB

__device__ unsigned g_hist[256];
__device__ unsigned g_prefix;
__device__ unsigned g_rank;
__device__ unsigned g_neq;
__device__ unsigned g_idxcut;
__device__ unsigned g_eqidx[EQ_CAP];

static __device__ __forceinline__ unsigned abs_bits(float v) {
    return __float_as_uint(fabsf(v));
}

// ======================= selection kernels =================================
__global__ void k_init() {
    int t = threadIdx.x;
    if (t < 256) g_hist[t] = 0;
    if (t == 0) { g_prefix = 0u; g_rank = JRANK; g_neq = 0u; g_idxcut = 0u; }
}

__global__ void k_hist(const float4* __restrict__ s4, int n4, int shift) {
    __shared__ unsigned sh[256];
    if (threadIdx.x < 256) sh[threadIdx.x] = 0;
    __syncthreads();
    const unsigned pref = g_prefix;
    const unsigned mask = (shift == 24) ? 0u : (0xFFFFFFFFu << (shift + 8));
    int stride = blockDim.x * gridDim.x;
    for (int i = blockIdx.x * blockDim.x + threadIdx.x; i < n4; i += stride) {
        float4 v = s4[i];
        unsigned b;
        b = abs_bits(v.x); if ((b & mask) == pref) atomicAdd(&sh[(b >> shift) & 255], 1u);
        b = abs_bits(v.y); if ((b & mask) == pref) atomicAdd(&sh[(b >> shift) & 255], 1u);
        b = abs_bits(v.z); if ((b & mask) == pref) atomicAdd(&sh[(b >> shift) & 255], 1u);
        b = abs_bits(v.w); if ((b & mask) == pref) atomicAdd(&sh[(b >> shift) & 255], 1u);
    }
    __syncthreads();
    if (threadIdx.x < 256 && sh[threadIdx.x])
        atomicAdd(&g_hist[threadIdx.x], sh[threadIdx.x]);
}

__global__ void k_pick(int shift) {
    unsigned r = g_rank, cum = 0;
    #pragma unroll 1
    for (int b = 0; b < 256; ++b) {
        unsigned c = g_hist[b];
        if (cum + c > r) { g_prefix |= ((unsigned)b) << shift; g_rank = r - cum; break; }
        cum += c;
    }
    for (int b = 0; b < 256; ++b) g_hist[b] = 0;
}

__global__ void k_gather(const float4* __restrict__ s4, int n4) {
    const unsigned tb = g_prefix;
    int stride = blockDim.x * gridDim.x;
    for (int i = blockIdx.x * blockDim.x + threadIdx.x; i < n4; i += stride) {
        float4 v = s4[i];
        unsigned base = (unsigned)i << 2;
        if (abs_bits(v.x) == tb) { unsigned p = atomicAdd(&g_neq, 1u); if (p < EQ_CAP) g_eqidx[p] = base + 0; }
        if (abs_bits(v.y) == tb) { unsigned p = atomicAdd(&g_neq, 1u); if (p < EQ_CAP) g_eqidx[p] = base + 1; }
        if (abs_bits(v.z) == tb) { unsigned p = atomicAdd(&g_neq, 1u); if (p < EQ_CAP) g_eqidx[p] = base + 2; }
        if (abs_bits(v.w) == tb) { unsigned p = atomicAdd(&g_neq, 1u); if (p < EQ_CAP) g_eqidx[p] = base + 3; }
    }
}

__global__ void k_select_cut() {
    unsigned m = min(g_neq, (unsigned)EQ_CAP);
    unsigned d = g_rank;
    if (threadIdx.x == 0) {
        if (d == 0u) g_idxcut = 0u;
        else if (d >= m) g_idxcut = 0xFFFFFFFFu;
    }
    if (d == 0u || d >= m) return;
    for (unsigned e = threadIdx.x; e < m; e += blockDim.x) {
        unsigned v = g_eqidx[e];
        unsigned rank = 0;
        for (unsigned f = 0; f < m; ++f) rank += (g_eqidx[f] < v);
        if (rank == d) g_idxcut = v;
    }
}

// ======================= split kernels =====================================
// masked W * 2^14 -> fp16 hi + fp16 residual (blocked layout)
__global__ void k_split_w(const float4* __restrict__ w4, const float4* __restrict__ s4, int n4) {
    const unsigned tb  = g_prefix;
    const unsigned cut = g_idxcut;
    int stride = blockDim.x * gridDim.x;
    for (int i = blockIdx.x * blockDim.x + threadIdx.x; i < n4; i += stride) {
        float4 wv = w4[i], sv = s4[i];
        unsigned fi = (unsigned)i << 2;
        float f[4];
        unsigned b0 = abs_bits(sv.x), b1 = abs_bits(sv.y), b2 = abs_bits(sv.z), b3 = abs_bits(sv.w);
        f[0] = (b0 > tb || (b0 == tb && fi + 0 >= cut)) ? wv.x : 0.0f;
        f[1] = (b1 > tb || (b1 == tb && fi + 1 >= cut)) ? wv.y : 0.0f;
        f[2] = (b2 > tb || (b2 == tb && fi + 2 >= cut)) ? wv.z : 0.0f;
        f[3] = (b3 > tb || (b3 == tb && fi + 3 >= cut)) ? wv.w : 0.0f;
        unsigned short h[4], l[4];
        #pragma unroll
        for (int c = 0; c < 4; ++c) {
            float g = f[c] * WSCALE;
            __half hh = __float2half_rn(g);
            __half ll = __float2half_rn(g - __half2float(hh));
            h[c] = __half_as_ushort(hh);
            l[c] = __half_as_ushort(ll);
        }
        uint2 ph, pl;
        ph.x = (unsigned)h[0] | ((unsigned)h[1] << 16);
        ph.y = (unsigned)h[2] | ((unsigned)h[3] << 16);
        pl.x = (unsigned)l[0] | ((unsigned)l[1] << 16);
        pl.y = (unsigned)l[2] | ((unsigned)l[3] << 16);
        unsigned row = fi >> 12, k = fi & 4095;
        unsigned bx = row >> 7, rl = row & 127;
        unsigned ks = k >> 5, kl = k & 31;
        unsigned cs = kl >> 3;
        size_t   blk = (size_t)(bx * 128 + ks) << 13;
        unsigned off = rl * 64 + (((cs ^ ((rl >> 1) & 3))) << 4) + (kl & 7) * 2;
        *(uint2*)((char*)g_bh + blk + off) = ph;
        *(uint2*)((char*)g_bl + blk + off) = pl;
    }
}

// x -> fp16 (blocked layout)
__global__ void k_split_a(const float4* __restrict__ x4, int n4) {
    int stride = blockDim.x * gridDim.x;
    for (int i = blockIdx.x * blockDim.x + threadIdx.x; i < n4; i += stride) {
        float4 v = x4[i];
        unsigned short h[4];
        h[0] = __half_as_ushort(__float2half_rn(v.x));
        h[1] = __half_as_ushort(__float2half_rn(v.y));
        h[2] = __half_as_ushort(__float2half_rn(v.z));
        h[3] = __half_as_ushort(__float2half_rn(v.w));
        uint2 ph;
        ph.x = (unsigned)h[0] | ((unsigned)h[1] << 16);
        ph.y = (unsigned)h[2] | ((unsigned)h[3] << 16);
        unsigned fi = (unsigned)i << 2;
        unsigned row = fi >> 12, k = fi & 4095;
        unsigned by = row >> 8, rl = row & 255;
        unsigned ks = k >> 5, kl = k & 31;
        unsigned cs = kl >> 3;
        size_t   blk = (size_t)(by * 128 + ks) << 14;
        unsigned off = rl * 64 + (((cs ^ ((rl >> 1) & 3))) << 4) + (kl & 7) * 2;
        *(uint2*)((char*)g_ah + blk + off) = ph;
    }
}

// ======================= GEMM ==============================================
// CTA tile 256(M) x 128(N), BK=32, 512 threads = 16 warps (4x4), warp 64x32.
// 2 MMA terms: Ah*Bh + Ah*Bl (single fp32 accumulator chain).
// 4-stage ring of 32 KB stages filled by cp.async.bulk.

#define STAGES      4
#define STAGE_BYTES 32768
#define SM_AH       0
#define SM_BH       16384
#define SM_BL       24576
#define SMEM_GEMM   (STAGES * STAGE_BYTES)    // 131072
#define KSTEPS      (K_DIM / 32)              // 128

#define LDSM4(r0, r1, r2, r3, addr) \
    asm volatile("ldmatrix.sync.aligned.m8n8.x4.shared.b16 {%0,%1,%2,%3}, [%4];" \
                 : "=r"(r0), "=r"(r1), "=r"(r2), "=r"(r3) : "r"(addr))

#define MMA_F16(d, a0, a1, a2, a3, b0, b1) \
    asm volatile("mma.sync.aligned.m16n8k16.row.col.f32.f16.f16.f32 " \
                 "{%0,%1,%2,%3}, {%4,%5,%6,%7}, {%8,%9}, {%0,%1,%2,%3};" \
                 : "+f"((d)[0]), "+f"((d)[1]), "+f"((d)[2]), "+f"((d)[3]) \
                 : "r"(a0), "r"(a1), "r"(a2), "r"(a3), "r"(b0), "r"(b1))

#define MBARRIER_INIT(mbar, cnt) \
    asm volatile("mbarrier.init.shared.b64 [%0], %1;" :: "r"((uint32_t)(mbar)), "r"((uint32_t)(cnt)) : "memory")
#define MBARRIER_EXPECT_TX(mbar, tx) \
    asm volatile("mbarrier.arrive.expect_tx.shared.b64 _, [%0], %1;" :: "r"((uint32_t)(mbar)), "r"((uint32_t)(tx)) : "memory")

#define MBARRIER_WAIT_PARITY(mbar_smem_addr, phase_parity) do { \
    uint32_t _mbar = (uint32_t)(mbar_smem_addr); \
    uint32_t _parity = (uint32_t)(phase_parity); \
    uint32_t _done; \
    asm volatile("{\n\t.reg .pred p;\n\t" \
        "mbarrier.try_wait.parity.acquire.cta.shared::cta.b64 p, [%1], %2;\n\t" \
        "selp.b32 %0, 1, 0, p;\n\t}" \
        : "=r"(_done) : "r"(_mbar), "r"(_parity) : "memory"); \
    if (!_done) { \
        asm volatile("{\n\t.reg .pred P1;\n\t" \
            "WAIT_LOOP_%=:\n\t" \
            "mbarrier.try_wait.parity.acquire.cta.shared::cta.b64 P1, [%0], %1, 0x989680;\n\t" \
            "@P1 bra.uni WAIT_DONE_%=;\n\t" \
            "bra.uni WAIT_LOOP_%=;\n\t" \
            "WAIT_DONE_%=:\n\t}" \
            :: "r"(_mbar), "r"(_parity) : "memory"); \
    } \
} while (0)

static __device__ __forceinline__ void bulk_g2s(uint32_t dst, const void* src,
                                                uint32_t bytes, uint32_t mbar) {
    asm volatile(
        "cp.async.bulk.shared::cluster.global.mbarrier::complete_tx::bytes [%0], [%1], %2, [%3];"
        :: "r"(dst), "l"(src), "r"(bytes), "r"(mbar) : "memory");
}

__global__ void __launch_bounds__(512, 1)
k_gemm(const float* __restrict__ bias, float* __restrict__ outp) {
    extern __shared__ __align__(16) char dsmem[];
    __shared__ __align__(8) unsigned long long s_mbar[STAGES];

    uint32_t sb, mb;
    asm("{ .reg .u64 t; cvta.to.shared.u64 t, %1; cvt.u32.u64 %0, t; }" : "=r"(sb) : "l"(dsmem));
    asm("{ .reg .u64 t; cvta.to.shared.u64 t, %1; cvt.u32.u64 %0, t; }" : "=r"(mb) : "l"(&s_mbar[0]));

    const int tid  = threadIdx.x;
    const int wid  = tid >> 5;
    const int lane = tid & 31;

    // raster swizzle: 1024 blocks = 4 groups x (8 by x 32 bx)
    const int bid = blockIdx.x;
    const int by  = (bid >> 8) * 8 + (bid & 7);
    const int bx  = (bid >> 3) & 31;

    const int wm = wid >> 2;                 // 0..3
    const int wn = wid & 3;                  // 0..3

    const char* gah = (const char*)g_ah + ((size_t)by * 128 << 14);
    const char* gbh = (const char*)g_bh + ((size_t)bx * 128 << 13);
    const char* gbl = (const char*)g_bl + ((size_t)bx * 128 << 13);

    // per-lane ldsm addressing
    uint32_t rowOffA[4], swzA[4];
    const uint32_t hiA = (lane >> 4) & 1;
    {
        int arow = wm * 64 + (lane & 15);
        #pragma unroll
        for (int mt = 0; mt < 4; ++mt) {
            int r = arow + mt * 16;
            rowOffA[mt] = (uint32_t)r * 64;
            swzA[mt]    = ((uint32_t)r >> 1) & 3;
        }
    }
    uint32_t rowOffB[2], swzB[2];
    const uint32_t hiB = (lane >> 3) & 1;
    {
        int brow_lo = ((lane >> 4) << 3) + (lane & 7);
        #pragma unroll
        for (int p = 0; p < 2; ++p) {
            int r = wn * 32 + p * 16 + brow_lo;
            rowOffB[p] = (uint32_t)r * 64;
            swzB[p]    = ((uint32_t)r >> 1) & 3;
        }
    }

    if (tid == 0) {
        #pragma unroll
        for (int s = 0; s < STAGES; ++s) MBARRIER_INIT(mb + s * 8, 1);
    }
    __syncthreads();

    if (tid == 0) {
        #pragma unroll
        for (int s = 0; s < 3; ++s) {
            uint32_t mbar = mb + s * 8;
            uint32_t dst  = sb + s * STAGE_BYTES;
            MBARRIER_EXPECT_TX(mbar, STAGE_BYTES);
            bulk_g2s(dst + SM_AH, gah + ((size_t)s << 14), 16384, mbar);
            bulk_g2s(dst + SM_BH, gbh + ((size_t)s << 13), 8192,  mbar);
            bulk_g2s(dst + SM_BL, gbl + ((size_t)s << 13), 8192,  mbar);
        }
    }

    float acc[4][4][4];
    #pragma unroll
    for (int i = 0; i < 4; ++i)
        #pragma unroll
        for (int j = 0; j < 4; ++j)
            #pragma unroll
            for (int e = 0; e < 4; ++e) acc[i][j][e] = 0.0f;

    #pragma unroll 1
    for (int s = 0; s < KSTEPS; ++s) {
        const int slot = s & 3;
        MBARRIER_WAIT_PARITY(mb + slot * 8, (s >> 2) & 1);

        uint32_t sbase = sb + (uint32_t)slot * STAGE_BYTES;
        #pragma unroll
        for (int ks = 0; ks < 2; ++ks) {
            const uint32_t ks2 = (uint32_t)ks << 1;
            uint32_t ah[4][4];
            #pragma unroll
            for (int mt = 0; mt < 4; ++mt) {
                uint32_t a = sbase + rowOffA[mt] + (((ks2 | hiA) ^ swzA[mt]) << 4);
                LDSM4(ah[mt][0], ah[mt][1], ah[mt][2], ah[mt][3], a + SM_AH);
            }
            #pragma unroll
            for (int p = 0; p < 2; ++p) {
                uint32_t bh[4], bl[4];
                uint32_t b = sbase + rowOffB[p] + (((ks2 | hiB) ^ swzB[p]) << 4);
                LDSM4(bh[0], bh[1], bh[2], bh[3], b + SM_BH);
                LDSM4(bl[0], bl[1], bl[2], bl[3], b + SM_BL);
                #pragma unroll
                for (int mt = 0; mt < 4; ++mt) {
                    float* d0 = acc[mt][2 * p];
                    float* d1 = acc[mt][2 * p + 1];
                    MMA_F16(d0, ah[mt][0], ah[mt][1], ah[mt][2], ah[mt][3], bh[0], bh[1]);
                    MMA_F16(d1, ah[mt][0], ah[mt][1], ah[mt][2], ah[mt][3], bh[2], bh[3]);
                    MMA_F16(d0, ah[mt][0], ah[mt][1], ah[mt][2], ah[mt][3], bl[0], bl[1]);
                    MMA_F16(d1, ah[mt][0], ah[mt][1], ah[mt][2], ah[mt][3], bl[2], bl[3]);
                }
            }
        }

        __syncthreads();   // all threads done with the slot being refilled
        if (tid == 0 && s + 3 < KSTEPS) {
            const int ns = s + 3;
            const int nslot = ns & 3;
            uint32_t mbar = mb + nslot * 8;
            uint32_t dst  = sb + (uint32_t)nslot * STAGE_BYTES;
            MBARRIER_EXPECT_TX(mbar, STAGE_BYTES);
            bulk_g2s(dst + SM_AH, gah + ((size_t)ns << 14), 16384, mbar);
            bulk_g2s(dst + SM_BH, gbh + ((size_t)ns << 13), 8192,  mbar);
            bulk_g2s(dst + SM_BL, gbl + ((size_t)ns << 13), 8192,  mbar);
        }
    }

    // ---- epilogue: undo W scale, add bias, store fp32 ----
    #pragma unroll
    for (int nt = 0; nt < 4; ++nt) {
        int col = bx * 128 + wn * 32 + nt * 8 + (lane & 3) * 2;
        float2 bv = *(const float2*)(bias + col);
        #pragma unroll
        for (int mt = 0; mt < 4; ++mt) {
            int r0 = by * 256 + wm * 64 + mt * 16 + (lane >> 2);
            float2 o0, o1;
            o0.x = fmaf(acc[mt][nt][0], INV_WSCALE, bv.x);
            o0.y = fmaf(acc[mt][nt][1], INV_WSCALE, bv.y);
            o1.x = fmaf(acc[mt][nt][2], INV_WSCALE, bv.x);
            o1.y = fmaf(acc[mt][nt][3], INV_WSCALE, bv.y);
            *(float2*)(outp + (size_t)r0 * N_DIM + col)       = o0;
            *(float2*)(outp + (size_t)(r0 + 8) * N_DIM + col) = o1;
        }
    }
}

// ===========================================================================
extern "C" void kernel_launch(void* const* d_in, const int* in_sizes, int n_in,
                              void* d_out, int out_size) {
    const float* x    = (const float*)d_in[0];
    const float* w    = (const float*)d_in[1];
    const float* bias = (const float*)d_in[2];
    const float* s    = (const float*)d_in[3];
    float* out = (float*)d_out;

    k_init<<<1, 256>>>();
    for (int shift = 24; shift >= 0; shift -= 8) {
        k_hist<<<1024, 256>>>((const float4*)s, NTOT / 4, shift);
        k_pick<<<1, 1>>>(shift);
    }
    k_gather<<<1024, 256>>>((const float4*)s, NTOT / 4);
    k_select_cut<<<1, 256>>>();

    k_split_w<<<2048, 256>>>((const float4*)w, (const float4*)s, NTOT / 4);
    k_split_a<<<4096, 256>>>((const float4*)x, (M_DIM * K_DIM) / 4);

    cudaFuncSetAttribute(k_gemm, cudaFuncAttributeMaxDynamicSharedMemorySize, SMEM_GEMM);
    k_gemm<<<1024, 512, SMEM_GEMM>>>(bias, out);
}

// round 8
// speedup vs baseline: 7.0395x; 1.4767x over previous
#include <cuda_runtime.h>
#include <cuda_fp16.h>
#include <cstdint>

// ===========================================================================
// WeightPopupLayer: out = x @ (W * topk_mask(|scores|, 50%)).T + bias
// Round 8: single fp16 term. A = fp16(x); B = fp16(W*2^14 * mask) (normal
// range). One fp32-accum HMMA chain (67M MMA); epilogue scales by 2^-14.
// Exact radix-select mask unchanged. 8-stage cp.async.bulk ring, 24 KB/stage.
// ===========================================================================

#define NTOT   (4096 * 4096)
#define JRANK  8388608u
#define EQ_CAP (1 << 20)

#define M_DIM 8192
#define N_DIM 4096
#define K_DIM 4096

#define WSCALE     16384.0f
#define INV_WSCALE (1.0f / 16384.0f)

// Blocked scratch (fp16):
//   g_ah: [by=32][ks=128] blocks of 256 rows x 64B = 16384 B
//   g_bh: [bx=32][ks=128] blocks of 128 rows x 64B =  8192 B
// In-block: off = rl*64 + ((cs ^ ((rl>>1)&3)) << 4) + (kl&7)*2
__device__ __align__(16) __half g_ah[M_DIM * K_DIM];   // 64 MB
__device__ __align__(16) __half g_bh[N_DIM * K_DIM];   // 32 MB

__device__ unsigned g_hist[256];
__device__ unsigned g_prefix;
__device__ unsigned g_rank;
__device__ unsigned g_neq;
__device__ unsigned g_idxcut;
__device__ unsigned g_eqidx[EQ_CAP];

static __device__ __forceinline__ unsigned abs_bits(float v) {
    return __float_as_uint(fabsf(v));
}

// ======================= selection kernels =================================
__global__ void k_init() {
    int t = threadIdx.x;
    if (t < 256) g_hist[t] = 0;
    if (t == 0) { g_prefix = 0u; g_rank = JRANK; g_neq = 0u; g_idxcut = 0u; }
}

__global__ void k_hist(const float4* __restrict__ s4, int n4, int shift) {
    __shared__ unsigned sh[256];
    if (threadIdx.x < 256) sh[threadIdx.x] = 0;
    __syncthreads();
    const unsigned pref = g_prefix;
    const unsigned mask = (shift == 24) ? 0u : (0xFFFFFFFFu << (shift + 8));
    int stride = blockDim.x * gridDim.x;
    for (int i = blockIdx.x * blockDim.x + threadIdx.x; i < n4; i += stride) {
        float4 v = s4[i];
        unsigned b;
        b = abs_bits(v.x); if ((b & mask) == pref) atomicAdd(&sh[(b >> shift) & 255], 1u);
        b = abs_bits(v.y); if ((b & mask) == pref) atomicAdd(&sh[(b >> shift) & 255], 1u);
        b = abs_bits(v.z); if ((b & mask) == pref) atomicAdd(&sh[(b >> shift) & 255], 1u);
        b = abs_bits(v.w); if ((b & mask) == pref) atomicAdd(&sh[(b >> shift) & 255], 1u);
    }
    __syncthreads();
    if (threadIdx.x < 256 && sh[threadIdx.x])
        atomicAdd(&g_hist[threadIdx.x], sh[threadIdx.x]);
}

__global__ void k_pick(int shift) {
    unsigned r = g_rank, cum = 0;
    #pragma unroll 1
    for (int b = 0; b < 256; ++b) {
        unsigned c = g_hist[b];
        if (cum + c > r) { g_prefix |= ((unsigned)b) << shift; g_rank = r - cum; break; }
        cum += c;
    }
    for (int b = 0; b < 256; ++b) g_hist[b] = 0;
}

__global__ void k_gather(const float4* __restrict__ s4, int n4) {
    const unsigned tb = g_prefix;
    int stride = blockDim.x * gridDim.x;
    for (int i = blockIdx.x * blockDim.x + threadIdx.x; i < n4; i += stride) {
        float4 v = s4[i];
        unsigned base = (unsigned)i << 2;
        if (abs_bits(v.x) == tb) { unsigned p = atomicAdd(&g_neq, 1u); if (p < EQ_CAP) g_eqidx[p] = base + 0; }
        if (abs_bits(v.y) == tb) { unsigned p = atomicAdd(&g_neq, 1u); if (p < EQ_CAP) g_eqidx[p] = base + 1; }
        if (abs_bits(v.z) == tb) { unsigned p = atomicAdd(&g_neq, 1u); if (p < EQ_CAP) g_eqidx[p] = base + 2; }
        if (abs_bits(v.w) == tb) { unsigned p = atomicAdd(&g_neq, 1u); if (p < EQ_CAP) g_eqidx[p] = base + 3; }
    }
}

__global__ void k_select_cut() {
    unsigned m = min(g_neq, (unsigned)EQ_CAP);
    unsigned d = g_rank;
    if (threadIdx.x == 0) {
        if (d == 0u) g_idxcut = 0u;
        else if (d >= m) g_idxcut = 0xFFFFFFFFu;
    }
    if (d == 0u || d >= m) return;
    for (unsigned e = threadIdx.x; e < m; e += blockDim.x) {
        unsigned v = g_eqidx[e];
        unsigned rank = 0;
        for (unsigned f = 0; f < m; ++f) rank += (g_eqidx[f] < v);
        if (rank == d) g_idxcut = v;
    }
}

// ======================= split kernels =====================================
// masked W * 2^14 -> fp16 (blocked layout)
__global__ void k_split_w(const float4* __restrict__ w4, const float4* __restrict__ s4, int n4) {
    const unsigned tb  = g_prefix;
    const unsigned cut = g_idxcut;
    int stride = blockDim.x * gridDim.x;
    for (int i = blockIdx.x * blockDim.x + threadIdx.x; i < n4; i += stride) {
        float4 wv = w4[i], sv = s4[i];
        unsigned fi = (unsigned)i << 2;
        float f[4];
        unsigned b0 = abs_bits(sv.x), b1 = abs_bits(sv.y), b2 = abs_bits(sv.z), b3 = abs_bits(sv.w);
        f[0] = (b0 > tb || (b0 == tb && fi + 0 >= cut)) ? wv.x : 0.0f;
        f[1] = (b1 > tb || (b1 == tb && fi + 1 >= cut)) ? wv.y : 0.0f;
        f[2] = (b2 > tb || (b2 == tb && fi + 2 >= cut)) ? wv.z : 0.0f;
        f[3] = (b3 > tb || (b3 == tb && fi + 3 >= cut)) ? wv.w : 0.0f;
        unsigned short h[4];
        #pragma unroll
        for (int c = 0; c < 4; ++c)
            h[c] = __half_as_ushort(__float2half_rn(f[c] * WSCALE));
        uint2 ph;
        ph.x = (unsigned)h[0] | ((unsigned)h[1] << 16);
        ph.y = (unsigned)h[2] | ((unsigned)h[3] << 16);
        unsigned row = fi >> 12, k = fi & 4095;
        unsigned bx = row >> 7, rl = row & 127;
        unsigned ks = k >> 5, kl = k & 31;
        unsigned cs = kl >> 3;
        size_t   blk = (size_t)(bx * 128 + ks) << 13;
        unsigned off = rl * 64 + (((cs ^ ((rl >> 1) & 3))) << 4) + (kl & 7) * 2;
        *(uint2*)((char*)g_bh + blk + off) = ph;
    }
}

// x -> fp16 (blocked layout)
__global__ void k_split_a(const float4* __restrict__ x4, int n4) {
    int stride = blockDim.x * gridDim.x;
    for (int i = blockIdx.x * blockDim.x + threadIdx.x; i < n4; i += stride) {
        float4 v = x4[i];
        unsigned short h[4];
        h[0] = __half_as_ushort(__float2half_rn(v.x));
        h[1] = __half_as_ushort(__float2half_rn(v.y));
        h[2] = __half_as_ushort(__float2half_rn(v.z));
        h[3] = __half_as_ushort(__float2half_rn(v.w));
        uint2 ph;
        ph.x = (unsigned)h[0] | ((unsigned)h[1] << 16);
        ph.y = (unsigned)h[2] | ((unsigned)h[3] << 16);
        unsigned fi = (unsigned)i << 2;
        unsigned row = fi >> 12, k = fi & 4095;
        unsigned by = row >> 8, rl = row & 255;
        unsigned ks = k >> 5, kl = k & 31;
        unsigned cs = kl >> 3;
        size_t   blk = (size_t)(by * 128 + ks) << 14;
        unsigned off = rl * 64 + (((cs ^ ((rl >> 1) & 3))) << 4) + (kl & 7) * 2;
        *(uint2*)((char*)g_ah + blk + off) = ph;
    }
}

// ======================= GEMM ==============================================
// CTA tile 256(M) x 128(N), BK=32, 512 threads = 16 warps (4x4), warp 64x32.
// Single fp16 MMA term; 8-stage ring of 24 KB stages via cp.async.bulk.

#define STAGES      8
#define STAGE_BYTES 24576
#define SM_AH       0
#define SM_BH       16384
#define SMEM_GEMM   (STAGES * STAGE_BYTES)    // 196608
#define KSTEPS      (K_DIM / 32)              // 128

#define LDSM4(r0, r1, r2, r3, addr) \
    asm volatile("ldmatrix.sync.aligned.m8n8.x4.shared.b16 {%0,%1,%2,%3}, [%4];" \
                 : "=r"(r0), "=r"(r1), "=r"(r2), "=r"(r3) : "r"(addr))

#define MMA_F16(d, a0, a1, a2, a3, b0, b1) \
    asm volatile("mma.sync.aligned.m16n8k16.row.col.f32.f16.f16.f32 " \
                 "{%0,%1,%2,%3}, {%4,%5,%6,%7}, {%8,%9}, {%0,%1,%2,%3};" \
                 : "+f"((d)[0]), "+f"((d)[1]), "+f"((d)[2]), "+f"((d)[3]) \
                 : "r"(a0), "r"(a1), "r"(a2), "r"(a3), "r"(b0), "r"(b1))

#define MBARRIER_INIT(mbar, cnt) \
    asm volatile("mbarrier.init.shared.b64 [%0], %1;" :: "r"((uint32_t)(mbar)), "r"((uint32_t)(cnt)) : "memory")
#define MBARRIER_EXPECT_TX(mbar, tx) \
    asm volatile("mbarrier.arrive.expect_tx.shared.b64 _, [%0], %1;" :: "r"((uint32_t)(mbar)), "r"((uint32_t)(tx)) : "memory")

#define MBARRIER_WAIT_PARITY(mbar_smem_addr, phase_parity) do { \
    uint32_t _mbar = (uint32_t)(mbar_smem_addr); \
    uint32_t _parity = (uint32_t)(phase_parity); \
    uint32_t _done; \
    asm volatile("{\n\t.reg .pred p;\n\t" \
        "mbarrier.try_wait.parity.acquire.cta.shared::cta.b64 p, [%1], %2;\n\t" \
        "selp.b32 %0, 1, 0, p;\n\t}" \
        : "=r"(_done) : "r"(_mbar), "r"(_parity) : "memory"); \
    if (!_done) { \
        asm volatile("{\n\t.reg .pred P1;\n\t" \
            "WAIT_LOOP_%=:\n\t" \
            "mbarrier.try_wait.parity.acquire.cta.shared::cta.b64 P1, [%0], %1, 0x989680;\n\t" \
            "@P1 bra.uni WAIT_DONE_%=;\n\t" \
            "bra.uni WAIT_LOOP_%=;\n\t" \
            "WAIT_DONE_%=:\n\t}" \
            :: "r"(_mbar), "r"(_parity) : "memory"); \
    } \
} while (0)

static __device__ __forceinline__ void bulk_g2s(uint32_t dst, const void* src,
                                                uint32_t bytes, uint32_t mbar) {
    asm volatile(
        "cp.async.bulk.shared::cluster.global.mbarrier::complete_tx::bytes [%0], [%1], %2, [%3];"
        :: "r"(dst), "l"(src), "r"(bytes), "r"(mbar) : "memory");
}

__global__ void __launch_bounds__(512, 1)
k_gemm(const float* __restrict__ bias, float* __restrict__ outp) {
    extern __shared__ __align__(16) char dsmem[];
    __shared__ __align__(8) unsigned long long s_mbar[STAGES];

    uint32_t sb, mb;
    asm("{ .reg .u64 t; cvta.to.shared.u64 t, %1; cvt.u32.u64 %0, t; }" : "=r"(sb) : "l"(dsmem));
    asm("{ .reg .u64 t; cvta.to.shared.u64 t, %1; cvt.u32.u64 %0, t; }" : "=r"(mb) : "l"(&s_mbar[0]));

    const int tid  = threadIdx.x;
    const int wid  = tid >> 5;
    const int lane = tid & 31;

    // raster swizzle: 1024 blocks = 4 groups x (8 by x 32 bx)
    const int bid = blockIdx.x;
    const int by  = (bid >> 8) * 8 + (bid & 7);
    const int bx  = (bid >> 3) & 31;

    const int wm = wid >> 2;                 // 0..3
    const int wn = wid & 3;                  // 0..3

    const char* gah = (const char*)g_ah + ((size_t)by * 128 << 14);
    const char* gbh = (const char*)g_bh + ((size_t)bx * 128 << 13);

    // per-lane ldsm addressing
    uint32_t rowOffA[4], swzA[4];
    const uint32_t hiA = (lane >> 4) & 1;
    {
        int arow = wm * 64 + (lane & 15);
        #pragma unroll
        for (int mt = 0; mt < 4; ++mt) {
            int r = arow + mt * 16;
            rowOffA[mt] = (uint32_t)r * 64;
            swzA[mt]    = ((uint32_t)r >> 1) & 3;
        }
    }
    uint32_t rowOffB[2], swzB[2];
    const uint32_t hiB = (lane >> 3) & 1;
    {
        int brow_lo = ((lane >> 4) << 3) + (lane & 7);
        #pragma unroll
        for (int p = 0; p < 2; ++p) {
            int r = wn * 32 + p * 16 + brow_lo;
            rowOffB[p] = (uint32_t)r * 64;
            swzB[p]    = ((uint32_t)r >> 1) & 3;
        }
    }

    if (tid == 0) {
        #pragma unroll
        for (int s = 0; s < STAGES; ++s) MBARRIER_INIT(mb + s * 8, 1);
    }
    __syncthreads();

    if (tid == 0) {
        #pragma unroll
        for (int s = 0; s < STAGES - 1; ++s) {
            uint32_t mbar = mb + s * 8;
            uint32_t dst  = sb + s * STAGE_BYTES;
            MBARRIER_EXPECT_TX(mbar, STAGE_BYTES);
            bulk_g2s(dst + SM_AH, gah + ((size_t)s << 14), 16384, mbar);
            bulk_g2s(dst + SM_BH, gbh + ((size_t)s << 13), 8192,  mbar);
        }
    }

    float acc[4][4][4];
    #pragma unroll
    for (int i = 0; i < 4; ++i)
        #pragma unroll
        for (int j = 0; j < 4; ++j)
            #pragma unroll
            for (int e = 0; e < 4; ++e) acc[i][j][e] = 0.0f;

    #pragma unroll 1
    for (int s = 0; s < KSTEPS; ++s) {
        const int slot = s & (STAGES - 1);
        MBARRIER_WAIT_PARITY(mb + slot * 8, (s >> 3) & 1);

        uint32_t sbase = sb + (uint32_t)slot * STAGE_BYTES;
        #pragma unroll
        for (int ks = 0; ks < 2; ++ks) {
            const uint32_t ks2 = (uint32_t)ks << 1;
            uint32_t ah[4][4];
            #pragma unroll
            for (int mt = 0; mt < 4; ++mt) {
                uint32_t a = sbase + rowOffA[mt] + (((ks2 | hiA) ^ swzA[mt]) << 4);
                LDSM4(ah[mt][0], ah[mt][1], ah[mt][2], ah[mt][3], a + SM_AH);
            }
            #pragma unroll
            for (int p = 0; p < 2; ++p) {
                uint32_t bh[4];
                uint32_t b = sbase + rowOffB[p] + (((ks2 | hiB) ^ swzB[p]) << 4);
                LDSM4(bh[0], bh[1], bh[2], bh[3], b + SM_BH);
                #pragma unroll
                for (int mt = 0; mt < 4; ++mt) {
                    MMA_F16(acc[mt][2 * p],     ah[mt][0], ah[mt][1], ah[mt][2], ah[mt][3], bh[0], bh[1]);
                    MMA_F16(acc[mt][2 * p + 1], ah[mt][0], ah[mt][1], ah[mt][2], ah[mt][3], bh[2], bh[3]);
                }
            }
        }

        __syncthreads();   // all warps done with the slot being refilled
        if (tid == 0 && s + STAGES - 1 < KSTEPS) {
            const int ns = s + STAGES - 1;
            const int nslot = ns & (STAGES - 1);
            uint32_t mbar = mb + nslot * 8;
            uint32_t dst  = sb + (uint32_t)nslot * STAGE_BYTES;
            MBARRIER_EXPECT_TX(mbar, STAGE_BYTES);
            bulk_g2s(dst + SM_AH, gah + ((size_t)ns << 14), 16384, mbar);
            bulk_g2s(dst + SM_BH, gbh + ((size_t)ns << 13), 8192,  mbar);
        }
    }

    // ---- epilogue: undo W scale, add bias, store fp32 ----
    #pragma unroll
    for (int nt = 0; nt < 4; ++nt) {
        int col = bx * 128 + wn * 32 + nt * 8 + (lane & 3) * 2;
        float2 bv = *(const float2*)(bias + col);
        #pragma unroll
        for (int mt = 0; mt < 4; ++mt) {
            int r0 = by * 256 + wm * 64 + mt * 16 + (lane >> 2);
            float2 o0, o1;
            o0.x = fmaf(acc[mt][nt][0], INV_WSCALE, bv.x);
            o0.y = fmaf(acc[mt][nt][1], INV_WSCALE, bv.y);
            o1.x = fmaf(acc[mt][nt][2], INV_WSCALE, bv.x);
            o1.y = fmaf(acc[mt][nt][3], INV_WSCALE, bv.y);
            *(float2*)(outp + (size_t)r0 * N_DIM + col)       = o0;
            *(float2*)(outp + (size_t)(r0 + 8) * N_DIM + col) = o1;
        }
    }
}

// ===========================================================================
extern "C" void kernel_launch(void* const* d_in, const int* in_sizes, int n_in,
                              void* d_out, int out_size) {
    const float* x    = (const float*)d_in[0];
    const float* w    = (const float*)d_in[1];
    const float* bias = (const float*)d_in[2];
    const float* s    = (const float*)d_in[3];
    float* out = (float*)d_out;

    k_init<<<1, 256>>>();
    for (int shift = 24; shift >= 0; shift -= 8) {
        k_hist<<<1024, 256>>>((const float4*)s, NTOT / 4, shift);
        k_pick<<<1, 1>>>(shift);
    }
    k_gather<<<1024, 256>>>((const float4*)s, NTOT / 4);
    k_select_cut<<<1, 256>>>();

    k_split_w<<<2048, 256>>>((const float4*)w, (const float4*)s, NTOT / 4);
    k_split_a<<<4096, 256>>>((const float4*)x, (M_DIM * K_DIM) / 4);

    cudaFuncSetAttribute(k_gemm, cudaFuncAttributeMaxDynamicSharedMemorySize, SMEM_GEMM);
    k_gemm<<<1024, 512, SMEM_GEMM>>>(bias, out);
}

// round 9
// speedup vs baseline: 7.8200x; 1.1109x over previous
#include <cuda_runtime.h>
#include <cuda_fp16.h>
#include <cstdint>

// ===========================================================================
// WeightPopupLayer: out = x @ (W * topk_mask(|scores|, 50%)).T + bias
// Round 9: single fp16 term (A=fp16(x), B=fp16(W*2^14*mask), fp32 accum,
// epilogue *2^-14). GEMM: 256x128 CTA tile, 4-stage x 48KB ring, 64 K-cols
// per stage (2 merged k-steps -> half the syncs, half the DMA ops).
// Prep: run-length-aggregated radix histograms, 2x-unrolled streaming.
// ===========================================================================

#define NTOT   (4096 * 4096)
#define JRANK  8388608u
#define EQ_CAP (1 << 20)

#define M_DIM 8192
#define N_DIM 4096
#define K_DIM 4096

#define WSCALE     16384.0f
#define INV_WSCALE (1.0f / 16384.0f)

// Blocked scratch (fp16):
//   g_ah: [by=32][ks=128] blocks of 256 rows x 64B = 16384 B
//   g_bh: [bx=32][ks=128] blocks of 128 rows x 64B =  8192 B
// In-block: off = rl*64 + ((cs ^ ((rl>>1)&3)) << 4) + (kl&7)*2
__device__ __align__(16) __half g_ah[M_DIM * K_DIM];   // 64 MB
__device__ __align__(16) __half g_bh[N_DIM * K_DIM];   // 32 MB

__device__ unsigned g_hist[256];
__device__ unsigned g_prefix;
__device__ unsigned g_rank;
__device__ unsigned g_neq;
__device__ unsigned g_idxcut;
__device__ unsigned g_eqidx[EQ_CAP];

static __device__ __forceinline__ unsigned abs_bits(float v) {
    return __float_as_uint(fabsf(v));
}

// ======================= selection kernels =================================
__global__ void k_init() {
    int t = threadIdx.x;
    if (t < 256) g_hist[t] = 0;
    if (t == 0) { g_prefix = 0u; g_rank = JRANK; g_neq = 0u; g_idxcut = 0u; }
}

// run-length aggregated histogram: flush shared atomic only on bin change
__global__ void k_hist(const float4* __restrict__ s4, int n4, int shift) {
    __shared__ unsigned sh[256];
    if (threadIdx.x < 256) sh[threadIdx.x] = 0;
    __syncthreads();
    const unsigned pref = g_prefix;
    const unsigned mask = (shift == 24) ? 0u : (0xFFFFFFFFu << (shift + 8));
    int stride = blockDim.x * gridDim.x;
    unsigned cur = 0xFFFFFFFFu, cnt = 0;
    for (int i = blockIdx.x * blockDim.x + threadIdx.x; i < n4; i += stride) {
        float4 v = s4[i];
        unsigned bb[4] = {abs_bits(v.x), abs_bits(v.y), abs_bits(v.z), abs_bits(v.w)};
        #pragma unroll
        for (int c = 0; c < 4; ++c) {
            if ((bb[c] & mask) == pref) {
                unsigned bin = (bb[c] >> shift) & 255u;
                if (bin == cur) { ++cnt; }
                else {
                    if (cnt) atomicAdd(&sh[cur], cnt);
                    cur = bin; cnt = 1;
                }
            }
        }
    }
    if (cnt) atomicAdd(&sh[cur], cnt);
    __syncthreads();
    if (threadIdx.x < 256 && sh[threadIdx.x])
        atomicAdd(&g_hist[threadIdx.x], sh[threadIdx.x]);
}

__global__ void k_pick(int shift) {
    unsigned r = g_rank, cum = 0;
    #pragma unroll 1
    for (int b = 0; b < 256; ++b) {
        unsigned c = g_hist[b];
        if (cum + c > r) { g_prefix |= ((unsigned)b) << shift; g_rank = r - cum; break; }
        cum += c;
    }
    for (int b = 0; b < 256; ++b) g_hist[b] = 0;
}

__global__ void k_gather(const float4* __restrict__ s4, int n4) {
    const unsigned tb = g_prefix;
    int stride = blockDim.x * gridDim.x;
    for (int i = blockIdx.x * blockDim.x + threadIdx.x; i < n4; i += stride) {
        float4 v = s4[i];
        unsigned base = (unsigned)i << 2;
        if (abs_bits(v.x) == tb) { unsigned p = atomicAdd(&g_neq, 1u); if (p < EQ_CAP) g_eqidx[p] = base + 0; }
        if (abs_bits(v.y) == tb) { unsigned p = atomicAdd(&g_neq, 1u); if (p < EQ_CAP) g_eqidx[p] = base + 1; }
        if (abs_bits(v.z) == tb) { unsigned p = atomicAdd(&g_neq, 1u); if (p < EQ_CAP) g_eqidx[p] = base + 2; }
        if (abs_bits(v.w) == tb) { unsigned p = atomicAdd(&g_neq, 1u); if (p < EQ_CAP) g_eqidx[p] = base + 3; }
    }
}

__global__ void k_select_cut() {
    unsigned m = min(g_neq, (unsigned)EQ_CAP);
    unsigned d = g_rank;
    if (threadIdx.x == 0) {
        if (d == 0u) g_idxcut = 0u;
        else if (d >= m) g_idxcut = 0xFFFFFFFFu;
    }
    if (d == 0u || d >= m) return;
    for (unsigned e = threadIdx.x; e < m; e += blockDim.x) {
        unsigned v = g_eqidx[e];
        unsigned rank = 0;
        for (unsigned f = 0; f < m; ++f) rank += (g_eqidx[f] < v);
        if (rank == d) g_idxcut = v;
    }
}

// ======================= split kernels =====================================
// masked W * 2^14 -> fp16 (blocked layout)
__global__ void k_split_w(const float4* __restrict__ w4, const float4* __restrict__ s4, int n4) {
    const unsigned tb  = g_prefix;
    const unsigned cut = g_idxcut;
    int stride = blockDim.x * gridDim.x;
    for (int i = blockIdx.x * blockDim.x + threadIdx.x; i < n4; i += stride) {
        float4 wv = w4[i], sv = s4[i];
        unsigned fi = (unsigned)i << 2;
        float f[4];
        unsigned b0 = abs_bits(sv.x), b1 = abs_bits(sv.y), b2 = abs_bits(sv.z), b3 = abs_bits(sv.w);
        f[0] = (b0 > tb || (b0 == tb && fi + 0 >= cut)) ? wv.x : 0.0f;
        f[1] = (b1 > tb || (b1 == tb && fi + 1 >= cut)) ? wv.y : 0.0f;
        f[2] = (b2 > tb || (b2 == tb && fi + 2 >= cut)) ? wv.z : 0.0f;
        f[3] = (b3 > tb || (b3 == tb && fi + 3 >= cut)) ? wv.w : 0.0f;
        unsigned short h[4];
        #pragma unroll
        for (int c = 0; c < 4; ++c)
            h[c] = __half_as_ushort(__float2half_rn(f[c] * WSCALE));
        uint2 ph;
        ph.x = (unsigned)h[0] | ((unsigned)h[1] << 16);
        ph.y = (unsigned)h[2] | ((unsigned)h[3] << 16);
        unsigned row = fi >> 12, k = fi & 4095;
        unsigned bx = row >> 7, rl = row & 127;
        unsigned ks = k >> 5, kl = k & 31;
        unsigned cs = kl >> 3;
        size_t   blk = (size_t)(bx * 128 + ks) << 13;
        unsigned off = rl * 64 + (((cs ^ ((rl >> 1) & 3))) << 4) + (kl & 7) * 2;
        *(uint2*)((char*)g_bh + blk + off) = ph;
    }
}

// x -> fp16 (blocked layout)
__global__ void k_split_a(const float4* __restrict__ x4, int n4) {
    int stride = blockDim.x * gridDim.x;
    for (int i = blockIdx.x * blockDim.x + threadIdx.x; i < n4; i += stride) {
        float4 v = x4[i];
        unsigned short h[4];
        h[0] = __half_as_ushort(__float2half_rn(v.x));
        h[1] = __half_as_ushort(__float2half_rn(v.y));
        h[2] = __half_as_ushort(__float2half_rn(v.z));
        h[3] = __half_as_ushort(__float2half_rn(v.w));
        uint2 ph;
        ph.x = (unsigned)h[0] | ((unsigned)h[1] << 16);
        ph.y = (unsigned)h[2] | ((unsigned)h[3] << 16);
        unsigned fi = (unsigned)i << 2;
        unsigned row = fi >> 12, k = fi & 4095;
        unsigned by = row >> 8, rl = row & 255;
        unsigned ks = k >> 5, kl = k & 31;
        unsigned cs = kl >> 3;
        size_t   blk = (size_t)(by * 128 + ks) << 14;
        unsigned off = rl * 64 + (((cs ^ ((rl >> 1) & 3))) << 4) + (kl & 7) * 2;
        *(uint2*)((char*)g_ah + blk + off) = ph;
    }
}

// ======================= GEMM ==============================================
// CTA tile 256(M) x 128(N); 512 threads = 16 warps (4x4), warp 64x32.
// Stage = 64 K-columns (two 32-K blocks, contiguous in scratch):
//   A 32 KB @ 0, B 16 KB @ 32768 -> 48 KB; 4-stage ring = 192 KB.
// 64 outer iterations (one mbar wait + one syncthreads each).

#define STAGES      4
#define STAGE_BYTES 49152
#define SM_AH       0
#define SM_BH       32768
#define SMEM_GEMM   (STAGES * STAGE_BYTES)    // 196608
#define OSTEPS      (K_DIM / 64)              // 64

#define LDSM4(r0, r1, r2, r3, addr) \
    asm volatile("ldmatrix.sync.aligned.m8n8.x4.shared.b16 {%0,%1,%2,%3}, [%4];" \
                 : "=r"(r0), "=r"(r1), "=r"(r2), "=r"(r3) : "r"(addr))

#define MMA_F16(d, a0, a1, a2, a3, b0, b1) \
    asm volatile("mma.sync.aligned.m16n8k16.row.col.f32.f16.f16.f32 " \
                 "{%0,%1,%2,%3}, {%4,%5,%6,%7}, {%8,%9}, {%0,%1,%2,%3};" \
                 : "+f"((d)[0]), "+f"((d)[1]), "+f"((d)[2]), "+f"((d)[3]) \
                 : "r"(a0), "r"(a1), "r"(a2), "r"(a3), "r"(b0), "r"(b1))

#define MBARRIER_INIT(mbar, cnt) \
    asm volatile("mbarrier.init.shared.b64 [%0], %1;" :: "r"((uint32_t)(mbar)), "r"((uint32_t)(cnt)) : "memory")
#define MBARRIER_EXPECT_TX(mbar, tx) \
    asm volatile("mbarrier.arrive.expect_tx.shared.b64 _, [%0], %1;" :: "r"((uint32_t)(mbar)), "r"((uint32_t)(tx)) : "memory")

#define MBARRIER_WAIT_PARITY(mbar_smem_addr, phase_parity) do { \
    uint32_t _mbar = (uint32_t)(mbar_smem_addr); \
    uint32_t _parity = (uint32_t)(phase_parity); \
    uint32_t _done; \
    asm volatile("{\n\t.reg .pred p;\n\t" \
        "mbarrier.try_wait.parity.acquire.cta.shared::cta.b64 p, [%1], %2;\n\t" \
        "selp.b32 %0, 1, 0, p;\n\t}" \
        : "=r"(_done) : "r"(_mbar), "r"(_parity) : "memory"); \
    if (!_done) { \
        asm volatile("{\n\t.reg .pred P1;\n\t" \
            "WAIT_LOOP_%=:\n\t" \
            "mbarrier.try_wait.parity.acquire.cta.shared::cta.b64 P1, [%0], %1, 0x989680;\n\t" \
            "@P1 bra.uni WAIT_DONE_%=;\n\t" \
            "bra.uni WAIT_LOOP_%=;\n\t" \
            "WAIT_DONE_%=:\n\t}" \
            :: "r"(_mbar), "r"(_parity) : "memory"); \
    } \
} while (0)

static __device__ __forceinline__ void bulk_g2s(uint32_t dst, const void* src,
                                                uint32_t bytes, uint32_t mbar) {
    asm volatile(
        "cp.async.bulk.shared::cluster.global.mbarrier::complete_tx::bytes [%0], [%1], %2, [%3];"
        :: "r"(dst), "l"(src), "r"(bytes), "r"(mbar) : "memory");
}

__global__ void __launch_bounds__(512, 1)
k_gemm(const float* __restrict__ bias, float* __restrict__ outp) {
    extern __shared__ __align__(16) char dsmem[];
    __shared__ __align__(8) unsigned long long s_mbar[STAGES];

    uint32_t sb, mb;
    asm("{ .reg .u64 t; cvta.to.shared.u64 t, %1; cvt.u32.u64 %0, t; }" : "=r"(sb) : "l"(dsmem));
    asm("{ .reg .u64 t; cvta.to.shared.u64 t, %1; cvt.u32.u64 %0, t; }" : "=r"(mb) : "l"(&s_mbar[0]));

    const int tid  = threadIdx.x;
    const int wid  = tid >> 5;
    const int lane = tid & 31;

    // raster swizzle: 1024 blocks = 4 groups x (8 by x 32 bx)
    const int bid = blockIdx.x;
    const int by  = (bid >> 8) * 8 + (bid & 7);
    const int bx  = (bid >> 3) & 31;

    const int wm = wid >> 2;                 // 0..3
    const int wn = wid & 3;                  // 0..3

    const char* gah = (const char*)g_ah + ((size_t)by * 128 << 14);
    const char* gbh = (const char*)g_bh + ((size_t)bx * 128 << 13);

    // per-lane ldsm addressing (within one 32-K block)
    uint32_t rowOffA[4], swzA[4];
    const uint32_t hiA = (lane >> 4) & 1;
    {
        int arow = wm * 64 + (lane & 15);
        #pragma unroll
        for (int mt = 0; mt < 4; ++mt) {
            int r = arow + mt * 16;
            rowOffA[mt] = (uint32_t)r * 64;
            swzA[mt]    = ((uint32_t)r >> 1) & 3;
        }
    }
    uint32_t rowOffB[2], swzB[2];
    const uint32_t hiB = (lane >> 3) & 1;
    {
        int brow_lo = ((lane >> 4) << 3) + (lane & 7);
        #pragma unroll
        for (int p = 0; p < 2; ++p) {
            int r = wn * 32 + p * 16 + brow_lo;
            rowOffB[p] = (uint32_t)r * 64;
            swzB[p]    = ((uint32_t)r >> 1) & 3;
        }
    }

    if (tid == 0) {
        #pragma unroll
        for (int s = 0; s < STAGES; ++s) MBARRIER_INIT(mb + s * 8, 1);
    }
    __syncthreads();

    if (tid == 0) {
        #pragma unroll
        for (int s = 0; s < STAGES - 1; ++s) {
            uint32_t mbar = mb + s * 8;
            uint32_t dst  = sb + s * STAGE_BYTES;
            MBARRIER_EXPECT_TX(mbar, STAGE_BYTES);
            bulk_g2s(dst + SM_AH, gah + ((size_t)s << 15), 32768, mbar);
            bulk_g2s(dst + SM_BH, gbh + ((size_t)s << 14), 16384, mbar);
        }
    }

    float acc[4][4][4];
    #pragma unroll
    for (int i = 0; i < 4; ++i)
        #pragma unroll
        for (int j = 0; j < 4; ++j)
            #pragma unroll
            for (int e = 0; e < 4; ++e) acc[i][j][e] = 0.0f;

    #pragma unroll 1
    for (int s = 0; s < OSTEPS; ++s) {
        const int slot = s & (STAGES - 1);
        MBARRIER_WAIT_PARITY(mb + slot * 8, (s >> 2) & 1);

        uint32_t sbase = sb + (uint32_t)slot * STAGE_BYTES;
        #pragma unroll
        for (int half = 0; half < 2; ++half) {           // two 32-K blocks
            uint32_t abase = sbase + SM_AH + (uint32_t)half * 16384;
            uint32_t bbase = sbase + SM_BH + (uint32_t)half * 8192;
            #pragma unroll
            for (int ks = 0; ks < 2; ++ks) {             // two 16-K steps
                const uint32_t ks2 = (uint32_t)ks << 1;
                uint32_t ah[4][4];
                #pragma unroll
                for (int mt = 0; mt < 4; ++mt) {
                    uint32_t a = abase + rowOffA[mt] + (((ks2 | hiA) ^ swzA[mt]) << 4);
                    LDSM4(ah[mt][0], ah[mt][1], ah[mt][2], ah[mt][3], a);
                }
                #pragma unroll
                for (int p = 0; p < 2; ++p) {
                    uint32_t bh[4];
                    uint32_t b = bbase + rowOffB[p] + (((ks2 | hiB) ^ swzB[p]) << 4);
                    LDSM4(bh[0], bh[1], bh[2], bh[3], b);
                    #pragma unroll
                    for (int mt = 0; mt < 4; ++mt) {
                        MMA_F16(acc[mt][2 * p],     ah[mt][0], ah[mt][1], ah[mt][2], ah[mt][3], bh[0], bh[1]);
                        MMA_F16(acc[mt][2 * p + 1], ah[mt][0], ah[mt][1], ah[mt][2], ah[mt][3], bh[2], bh[3]);
                    }
                }
            }
        }

        __syncthreads();   // all warps done with the slot being refilled
        if (tid == 0 && s + STAGES - 1 < OSTEPS) {
            const int ns = s + STAGES - 1;
            const int nslot = ns & (STAGES - 1);
            uint32_t mbar = mb + nslot * 8;
            uint32_t dst  = sb + (uint32_t)nslot * STAGE_BYTES;
            MBARRIER_EXPECT_TX(mbar, STAGE_BYTES);
            bulk_g2s(dst + SM_AH, gah + ((size_t)ns << 15), 32768, mbar);
            bulk_g2s(dst + SM_BH, gbh + ((size_t)ns << 14), 16384, mbar);
        }
    }

    // ---- epilogue: undo W scale, add bias, store fp32 ----
    #pragma unroll
    for (int nt = 0; nt < 4; ++nt) {
        int col = bx * 128 + wn * 32 + nt * 8 + (lane & 3) * 2;
        float2 bv = *(const float2*)(bias + col);
        #pragma unroll
        for (int mt = 0; mt < 4; ++mt) {
            int r0 = by * 256 + wm * 64 + mt * 16 + (lane >> 2);
            float2 o0, o1;
            o0.x = fmaf(acc[mt][nt][0], INV_WSCALE, bv.x);
            o0.y = fmaf(acc[mt][nt][1], INV_WSCALE, bv.y);
            o1.x = fmaf(acc[mt][nt][2], INV_WSCALE, bv.x);
            o1.y = fmaf(acc[mt][nt][3], INV_WSCALE, bv.y);
            *(float2*)(outp + (size_t)r0 * N_DIM + col)       = o0;
            *(float2*)(outp + (size_t)(r0 + 8) * N_DIM + col) = o1;
        }
    }
}

// ===========================================================================
extern "C" void kernel_launch(void* const* d_in, const int* in_sizes, int n_in,
                              void* d_out, int out_size) {
    const float* x    = (const float*)d_in[0];
    const float* w    = (const float*)d_in[1];
    const float* bias = (const float*)d_in[2];
    const float* s    = (const float*)d_in[3];
    float* out = (float*)d_out;

    k_init<<<1, 256>>>();
    for (int shift = 24; shift >= 0; shift -= 8) {
        k_hist<<<1024, 256>>>((const float4*)s, NTOT / 4, shift);
        k_pick<<<1, 1>>>(shift);
    }
    k_gather<<<1024, 256>>>((const float4*)s, NTOT / 4);
    k_select_cut<<<1, 256>>>();

    k_split_w<<<2048, 256>>>((const float4*)w, (const float4*)s, NTOT / 4);
    k_split_a<<<4096, 256>>>((const float4*)x, (M_DIM * K_DIM) / 4);

    cudaFuncSetAttribute(k_gemm, cudaFuncAttributeMaxDynamicSharedMemorySize, SMEM_GEMM);
    k_gemm<<<1024, 512, SMEM_GEMM>>>(bias, out);
}

// round 10
// speedup vs baseline: 8.0505x; 1.0295x over previous
#include <cuda_runtime.h>
#include <cuda_fp16.h>
#include <cstdint>

// ===========================================================================
// WeightPopupLayer: out = x @ (W * topk_mask(|scores|, 50%)).T + bias
// Round 10: single fp16 term GEMM (A=fp16(x), B=fp16(W*2^14*mask), fp32
// accum, *2^-14). Persistent 148-CTA GEMM with continuous 4-stage bulk-DMA
// ring across tiles. Prep: simple 2x-unrolled radix scans; pass 4 compacts
// top-24 matches so the final byte + tie-gather + cut run on a tiny buffer.
// ===========================================================================

#define NTOT    (4096 * 4096)
#define JRANK   8388608u
#define CMP_CAP (1 << 22)
#define TIE_CAP 4096

#define M_DIM 8192
#define N_DIM 4096
#define K_DIM 4096

#define WSCALE     16384.0f
#define INV_WSCALE (1.0f / 16384.0f)

// Blocked fp16 scratch:
//   g_ah: [by=32][ks=128] blocks of 256 rows x 64B = 16384 B
//   g_bh: [bx=32][ks=128] blocks of 128 rows x 64B =  8192 B
// In-block: off = rl*64 + ((cs ^ ((rl>>1)&3)) << 4) + (kl&7)*2
__device__ __align__(16) __half g_ah[M_DIM * K_DIM];   // 64 MB
__device__ __align__(16) __half g_bh[N_DIM * K_DIM];   // 32 MB

__device__ unsigned g_hist[256];
__device__ unsigned g_prefix;
__device__ unsigned g_rank;
__device__ unsigned g_ncomp;
__device__ unsigned g_idxcut;
__device__ unsigned g_cmp_val[CMP_CAP];
__device__ unsigned g_cmp_idx[CMP_CAP];

static __device__ __forceinline__ unsigned abs_bits(float v) {
    return __float_as_uint(fabsf(v));
}

// ======================= selection kernels =================================
__global__ void k_init() {
    int t = threadIdx.x;
    if (t < 256) g_hist[t] = 0;
    if (t == 0) { g_prefix = 0u; g_rank = JRANK; g_ncomp = 0u; g_idxcut = 0u; }
}

// simple histogram scan, 2x float4 unrolled
__global__ void k_scan(const float4* __restrict__ s4, int n4, int shift) {
    __shared__ unsigned sh[256];
    if (threadIdx.x < 256) sh[threadIdx.x] = 0;
    __syncthreads();
    const unsigned pref = g_prefix;
    const unsigned mask = (shift == 24) ? 0u : (0xFFFFFFFFu << (shift + 8));
    int stride = blockDim.x * gridDim.x;
    for (int i = blockIdx.x * blockDim.x + threadIdx.x; i < n4; i += 2 * stride) {
        float4 v1 = s4[i];
        int j = i + stride;
        bool h2 = (j < n4);
        float4 v2 = h2 ? s4[j] : make_float4(0.f, 0.f, 0.f, 0.f);
        unsigned b;
        b = abs_bits(v1.x); if ((b & mask) == pref) atomicAdd(&sh[(b >> shift) & 255], 1u);
        b = abs_bits(v1.y); if ((b & mask) == pref) atomicAdd(&sh[(b >> shift) & 255], 1u);
        b = abs_bits(v1.z); if ((b & mask) == pref) atomicAdd(&sh[(b >> shift) & 255], 1u);
        b = abs_bits(v1.w); if ((b & mask) == pref) atomicAdd(&sh[(b >> shift) & 255], 1u);
        if (h2) {
            b = abs_bits(v2.x); if ((b & mask) == pref) atomicAdd(&sh[(b >> shift) & 255], 1u);
            b = abs_bits(v2.y); if ((b & mask) == pref) atomicAdd(&sh[(b >> shift) & 255], 1u);
            b = abs_bits(v2.z); if ((b & mask) == pref) atomicAdd(&sh[(b >> shift) & 255], 1u);
            b = abs_bits(v2.w); if ((b & mask) == pref) atomicAdd(&sh[(b >> shift) & 255], 1u);
        }
    }
    __syncthreads();
    if (threadIdx.x < 256 && sh[threadIdx.x])
        atomicAdd(&g_hist[threadIdx.x], sh[threadIdx.x]);
}

__global__ void k_pick(int shift) {
    unsigned r = g_rank, cum = 0;
    #pragma unroll 1
    for (int b = 0; b < 256; ++b) {
        unsigned c = g_hist[b];
        if (cum + c > r) { g_prefix |= ((unsigned)b) << shift; g_rank = r - cum; break; }
        cum += c;
    }
    for (int b = 0; b < 256; ++b) g_hist[b] = 0;
}

// pass 4: byte0 histogram of top-24 matches + warp-aggregated compaction
__global__ void k_scan4(const float4* __restrict__ s4, int n4) {
    __shared__ unsigned sh[256];
    if (threadIdx.x < 256) sh[threadIdx.x] = 0;
    __syncthreads();
    const unsigned pref = g_prefix;           // top 24 bits set, low byte 0
    const int lane = threadIdx.x & 31;
    int stride = blockDim.x * gridDim.x;
    for (int i = blockIdx.x * blockDim.x + threadIdx.x; i < n4; i += stride) {
        bool valid = (i < n4);
        float4 v = valid ? s4[i] : make_float4(0.f, 0.f, 0.f, 0.f);
        unsigned bb[4] = {abs_bits(v.x), abs_bits(v.y), abs_bits(v.z), abs_bits(v.w)};
        unsigned fi = (unsigned)i << 2;
        #pragma unroll
        for (int c = 0; c < 4; ++c) {
            bool match = valid && ((bb[c] & 0xFFFFFF00u) == pref);
            if (match) atomicAdd(&sh[bb[c] & 255u], 1u);
            unsigned mk = __ballot_sync(0xFFFFFFFFu, match);
            if (mk) {
                int leader = __ffs(mk) - 1;
                unsigned base = 0;
                if (lane == leader) base = atomicAdd(&g_ncomp, (unsigned)__popc(mk));
                base = __shfl_sync(0xFFFFFFFFu, base, leader);
                if (match) {
                    unsigned off = base + __popc(mk & ((1u << lane) - 1u));
                    if (off < CMP_CAP) { g_cmp_val[off] = bb[c]; g_cmp_idx[off] = fi + c; }
                }
            }
        }
    }
    __syncthreads();
    if (threadIdx.x < 256 && sh[threadIdx.x])
        atomicAdd(&g_hist[threadIdx.x], sh[threadIdx.x]);
}

// final: pick byte0 + tie gather + stable-argsort index cut (one block)
__global__ void k_final(const float* __restrict__ sfull) {
    __shared__ unsigned v[256], ps[256];
    __shared__ unsigned tie[TIE_CAP];
    __shared__ unsigned s_cnt;
    const int t = threadIdx.x;
    if (t == 0) s_cnt = 0;
    if (t < 256) { v[t] = g_hist[t]; ps[t] = v[t]; }
    __syncthreads();
    // inclusive prefix sum over 256 bins
    for (int off = 1; off < 256; off <<= 1) {
        unsigned add = 0;
        if (t < 256 && t >= off) add = ps[t - off];
        __syncthreads();
        if (t < 256) ps[t] += add;
        __syncthreads();
    }
    unsigned r = g_rank;
    __syncthreads();
    if (t < 256) {
        unsigned excl = ps[t] - v[t];
        if (r >= excl && r < ps[t]) { g_prefix |= (unsigned)t; g_rank = r - excl; }
    }
    __syncthreads();
    const unsigned tb = g_prefix;
    const unsigned d  = g_rank;
    const unsigned m  = g_ncomp;
    const bool ok = (m <= (unsigned)CMP_CAP);
    // gather flat indices of exact-threshold ties
    if (ok) {
        for (unsigned i = t; i < m; i += blockDim.x) {
            if (g_cmp_val[i] == tb) {
                unsigned p = atomicAdd(&s_cnt, 1u);
                if (p < TIE_CAP) tie[p] = g_cmp_idx[i];
            }
        }
    } else {   // overflow fallback: full scan (slow, correct)
        for (unsigned i = t; i < (unsigned)NTOT; i += blockDim.x) {
            if (abs_bits(sfull[i]) == tb) {
                unsigned p = atomicAdd(&s_cnt, 1u);
                if (p < TIE_CAP) tie[p] = i;
            }
        }
    }
    __syncthreads();
    unsigned mm = min(s_cnt, (unsigned)TIE_CAP);
    if (t == 0) {
        if (d == 0u) g_idxcut = 0u;
        else if (d >= mm) g_idxcut = 0xFFFFFFFFu;
    }
    if (!(d == 0u || d >= mm)) {
        for (unsigned e = t; e < mm; e += blockDim.x) {
            unsigned vv = tie[e];
            unsigned rank = 0;
            for (unsigned f = 0; f < mm; ++f) rank += (tie[f] < vv);
            if (rank == d) g_idxcut = vv;
        }
    }
}

// ======================= split kernels =====================================
// masked W * 2^14 -> fp16 (blocked layout)
__global__ void k_split_w(const float4* __restrict__ w4, const float4* __restrict__ s4, int n4) {
    const unsigned tb  = g_prefix;
    const unsigned cut = g_idxcut;
    int stride = blockDim.x * gridDim.x;
    for (int i = blockIdx.x * blockDim.x + threadIdx.x; i < n4; i += stride) {
        float4 wv = w4[i], sv = s4[i];
        unsigned fi = (unsigned)i << 2;
        float f[4];
        unsigned b0 = abs_bits(sv.x), b1 = abs_bits(sv.y), b2 = abs_bits(sv.z), b3 = abs_bits(sv.w);
        f[0] = (b0 > tb || (b0 == tb && fi + 0 >= cut)) ? wv.x : 0.0f;
        f[1] = (b1 > tb || (b1 == tb && fi + 1 >= cut)) ? wv.y : 0.0f;
        f[2] = (b2 > tb || (b2 == tb && fi + 2 >= cut)) ? wv.z : 0.0f;
        f[3] = (b3 > tb || (b3 == tb && fi + 3 >= cut)) ? wv.w : 0.0f;
        unsigned short h[4];
        #pragma unroll
        for (int c = 0; c < 4; ++c)
            h[c] = __half_as_ushort(__float2half_rn(f[c] * WSCALE));
        uint2 ph;
        ph.x = (unsigned)h[0] | ((unsigned)h[1] << 16);
        ph.y = (unsigned)h[2] | ((unsigned)h[3] << 16);
        unsigned row = fi >> 12, k = fi & 4095;
        unsigned bx = row >> 7, rl = row & 127;
        unsigned ks = k >> 5, kl = k & 31;
        unsigned cs = kl >> 3;
        size_t   blk = (size_t)(bx * 128 + ks) << 13;
        unsigned off = rl * 64 + (((cs ^ ((rl >> 1) & 3))) << 4) + (kl & 7) * 2;
        *(uint2*)((char*)g_bh + blk + off) = ph;
    }
}

// x -> fp16 (blocked layout)
__global__ void k_split_a(const float4* __restrict__ x4, int n4) {
    int stride = blockDim.x * gridDim.x;
    for (int i = blockIdx.x * blockDim.x + threadIdx.x; i < n4; i += stride) {
        float4 v = x4[i];
        unsigned short h[4];
        h[0] = __half_as_ushort(__float2half_rn(v.x));
        h[1] = __half_as_ushort(__float2half_rn(v.y));
        h[2] = __half_as_ushort(__float2half_rn(v.z));
        h[3] = __half_as_ushort(__float2half_rn(v.w));
        uint2 ph;
        ph.x = (unsigned)h[0] | ((unsigned)h[1] << 16);
        ph.y = (unsigned)h[2] | ((unsigned)h[3] << 16);
        unsigned fi = (unsigned)i << 2;
        unsigned row = fi >> 12, k = fi & 4095;
        unsigned by = row >> 8, rl = row & 255;
        unsigned ks = k >> 5, kl = k & 31;
        unsigned cs = kl >> 3;
        size_t   blk = (size_t)(by * 128 + ks) << 14;
        unsigned off = rl * 64 + (((cs ^ ((rl >> 1) & 3))) << 4) + (kl & 7) * 2;
        *(uint2*)((char*)g_ah + blk + off) = ph;
    }
}

// ======================= persistent GEMM ===================================
// 148 persistent CTAs, each ~7 tiles of 256(M)x128(N). 512 threads = 16
// warps (4x4), warp 64x32. 4-stage x 48 KB ring runs continuously across
// tile boundaries (global stage counter g; slot=g&3, parity=(g>>2)&1).

#define GRID_P      148
#define N_TILES     1024
#define STAGES      4
#define STAGE_BYTES 49152
#define SM_AH       0
#define SM_BH       32768
#define SMEM_GEMM   (STAGES * STAGE_BYTES)    // 196608
#define TSTEPS      64                        // 64-K stages per tile

#define LDSM4(r0, r1, r2, r3, addr) \
    asm volatile("ldmatrix.sync.aligned.m8n8.x4.shared.b16 {%0,%1,%2,%3}, [%4];" \
                 : "=r"(r0), "=r"(r1), "=r"(r2), "=r"(r3) : "r"(addr))

#define MMA_F16(d, a0, a1, a2, a3, b0, b1) \
    asm volatile("mma.sync.aligned.m16n8k16.row.col.f32.f16.f16.f32 " \
                 "{%0,%1,%2,%3}, {%4,%5,%6,%7}, {%8,%9}, {%0,%1,%2,%3};" \
                 : "+f"((d)[0]), "+f"((d)[1]), "+f"((d)[2]), "+f"((d)[3]) \
                 : "r"(a0), "r"(a1), "r"(a2), "r"(a3), "r"(b0), "r"(b1))

#define MBARRIER_INIT(mbar, cnt) \
    asm volatile("mbarrier.init.shared.b64 [%0], %1;" :: "r"((uint32_t)(mbar)), "r"((uint32_t)(cnt)) : "memory")
#define MBARRIER_EXPECT_TX(mbar, tx) \
    asm volatile("mbarrier.arrive.expect_tx.shared.b64 _, [%0], %1;" :: "r"((uint32_t)(mbar)), "r"((uint32_t)(tx)) : "memory")

#define MBARRIER_WAIT_PARITY(mbar_smem_addr, phase_parity) do { \
    uint32_t _mbar = (uint32_t)(mbar_smem_addr); \
    uint32_t _parity = (uint32_t)(phase_parity); \
    uint32_t _done; \
    asm volatile("{\n\t.reg .pred p;\n\t" \
        "mbarrier.try_wait.parity.acquire.cta.shared::cta.b64 p, [%1], %2;\n\t" \
        "selp.b32 %0, 1, 0, p;\n\t}" \
        : "=r"(_done) : "r"(_mbar), "r"(_parity) : "memory"); \
    if (!_done) { \
        asm volatile("{\n\t.reg .pred P1;\n\t" \
            "WAIT_LOOP_%=:\n\t" \
            "mbarrier.try_wait.parity.acquire.cta.shared::cta.b64 P1, [%0], %1, 0x989680;\n\t" \
            "@P1 bra.uni WAIT_DONE_%=;\n\t" \
            "bra.uni WAIT_LOOP_%=;\n\t" \
            "WAIT_DONE_%=:\n\t}" \
            :: "r"(_mbar), "r"(_parity) : "memory"); \
    } \
} while (0)

static __device__ __forceinline__ void bulk_g2s(uint32_t dst, const void* src,
                                                uint32_t bytes, uint32_t mbar) {
    asm volatile(
        "cp.async.bulk.shared::cluster.global.mbarrier::complete_tx::bytes [%0], [%1], %2, [%3];"
        :: "r"(dst), "l"(src), "r"(bytes), "r"(mbar) : "memory");
}

// tile id -> (by, bx) raster (identical locality to round 9)
static __device__ __forceinline__ void tile_coords(int tau, int& by, int& bx) {
    by = (tau >> 8) * 8 + (tau & 7);
    bx = (tau >> 3) & 31;
}

static __device__ __forceinline__ void issue_stage(uint32_t sb, uint32_t mb,
                                                   int p, int g) {
    int tn = g >> 6, sn = g & 63;
    int tau = p + tn * GRID_P;
    int byn, bxn;
    tile_coords(tau, byn, bxn);
    const char* pa = (const char*)g_ah + ((size_t)byn * 128 << 14) + ((size_t)sn << 15);
    const char* pb = (const char*)g_bh + ((size_t)bxn * 128 << 13) + ((size_t)sn << 14);
    uint32_t mbar = mb + (uint32_t)(g & (STAGES - 1)) * 8;
    uint32_t dst  = sb + (uint32_t)(g & (STAGES - 1)) * STAGE_BYTES;
    MBARRIER_EXPECT_TX(mbar, STAGE_BYTES);
    bulk_g2s(dst + SM_AH, pa, 32768, mbar);
    bulk_g2s(dst + SM_BH, pb, 16384, mbar);
}

__global__ void __launch_bounds__(512, 1)
k_gemm(const float* __restrict__ bias, float* __restrict__ outp) {
    extern __shared__ __align__(16) char dsmem[];
    __shared__ __align__(8) unsigned long long s_mbar[STAGES];

    uint32_t sb, mb;
    asm("{ .reg .u64 t; cvta.to.shared.u64 t, %1; cvt.u32.u64 %0, t; }" : "=r"(sb) : "l"(dsmem));
    asm("{ .reg .u64 t; cvta.to.shared.u64 t, %1; cvt.u32.u64 %0, t; }" : "=r"(mb) : "l"(&s_mbar[0]));

    const int tid  = threadIdx.x;
    const int wid  = tid >> 5;
    const int lane = tid & 31;
    const int p    = blockIdx.x;

    const int n_t  = (N_TILES - 1 - p) / GRID_P + 1;   // 6 or 7 tiles
    const int Gtot = n_t * TSTEPS;

    const int wm = wid >> 2;                 // 0..3
    const int wn = wid & 3;                  // 0..3

    // per-lane ldsm addressing (within one 32-K block)
    uint32_t rowOffA[4], swzA[4];
    const uint32_t hiA = (lane >> 4) & 1;
    {
        int arow = wm * 64 + (lane & 15);
        #pragma unroll
        for (int mt = 0; mt < 4; ++mt) {
            int r = arow + mt * 16;
            rowOffA[mt] = (uint32_t)r * 64;
            swzA[mt]    = ((uint32_t)r >> 1) & 3;
        }
    }
    uint32_t rowOffB[2], swzB[2];
    const uint32_t hiB = (lane >> 3) & 1;
    {
        int brow_lo = ((lane >> 4) << 3) + (lane & 7);
        #pragma unroll
        for (int pp = 0; pp < 2; ++pp) {
            int r = wn * 32 + pp * 16 + brow_lo;
            rowOffB[pp] = (uint32_t)r * 64;
            swzB[pp]    = ((uint32_t)r >> 1) & 3;
        }
    }

    if (tid == 0) {
        #pragma unroll
        for (int s = 0; s < STAGES; ++s) MBARRIER_INIT(mb + s * 8, 1);
    }
    __syncthreads();

    if (tid == 0) {
        #pragma unroll
        for (int g0 = 0; g0 < STAGES - 1; ++g0) issue_stage(sb, mb, p, g0);
    }

    int g = 0;
    #pragma unroll 1
    for (int t_idx = 0; t_idx < n_t; ++t_idx) {
        int tau = p + t_idx * GRID_P;
        int by, bx;
        tile_coords(tau, by, bx);

        float acc[4][4][4];
        #pragma unroll
        for (int i = 0; i < 4; ++i)
            #pragma unroll
            for (int j = 0; j < 4; ++j)
                #pragma unroll
                for (int e = 0; e < 4; ++e) acc[i][j][e] = 0.0f;

        #pragma unroll 1
        for (int s = 0; s < TSTEPS; ++s, ++g) {
            const int slot = g & (STAGES - 1);
            MBARRIER_WAIT_PARITY(mb + slot * 8, (g >> 2) & 1);

            uint32_t sbase = sb + (uint32_t)slot * STAGE_BYTES;
            #pragma unroll
            for (int half = 0; half < 2; ++half) {           // two 32-K blocks
                uint32_t abase = sbase + SM_AH + (uint32_t)half * 16384;
                uint32_t bbase = sbase + SM_BH + (uint32_t)half * 8192;
                #pragma unroll
                for (int ks = 0; ks < 2; ++ks) {             // two 16-K steps
                    const uint32_t ks2 = (uint32_t)ks << 1;
                    uint32_t ah[4][4];
                    #pragma unroll
                    for (int mt = 0; mt < 4; ++mt) {
                        uint32_t a = abase + rowOffA[mt] + (((ks2 | hiA) ^ swzA[mt]) << 4);
                        LDSM4(ah[mt][0], ah[mt][1], ah[mt][2], ah[mt][3], a);
                    }
                    #pragma unroll
                    for (int pp = 0; pp < 2; ++pp) {
                        uint32_t bh[4];
                        uint32_t b = bbase + rowOffB[pp] + (((ks2 | hiB) ^ swzB[pp]) << 4);
                        LDSM4(bh[0], bh[1], bh[2], bh[3], b);
                        #pragma unroll
                        for (int mt = 0; mt < 4; ++mt) {
                            MMA_F16(acc[mt][2 * pp],     ah[mt][0], ah[mt][1], ah[mt][2], ah[mt][3], bh[0], bh[1]);
                            MMA_F16(acc[mt][2 * pp + 1], ah[mt][0], ah[mt][1], ah[mt][2], ah[mt][3], bh[2], bh[3]);
                        }
                    }
                }
            }

            __syncthreads();   // all warps done with the slot being refilled
            if (tid == 0 && g + STAGES - 1 < Gtot)
                issue_stage(sb, mb, p, g + STAGES - 1);
        }

        // ---- epilogue: undo W scale, add bias, store fp32 ----
        #pragma unroll
        for (int nt = 0; nt < 4; ++nt) {
            int col = bx * 128 + wn * 32 + nt * 8 + (lane & 3) * 2;
            float2 bv = *(const float2*)(bias + col);
            #pragma unroll
            for (int mt = 0; mt < 4; ++mt) {
                int r0 = by * 256 + wm * 64 + mt * 16 + (lane >> 2);
                float2 o0, o1;
                o0.x = fmaf(acc[mt][nt][0], INV_WSCALE, bv.x);
                o0.y = fmaf(acc[mt][nt][1], INV_WSCALE, bv.y);
                o1.x = fmaf(acc[mt][nt][2], INV_WSCALE, bv.x);
                o1.y = fmaf(acc[mt][nt][3], INV_WSCALE, bv.y);
                *(float2*)(outp + (size_t)r0 * N_DIM + col)       = o0;
                *(float2*)(outp + (size_t)(r0 + 8) * N_DIM + col) = o1;
            }
        }
    }
}

// ===========================================================================
extern "C" void kernel_launch(void* const* d_in, const int* in_sizes, int n_in,
                              void* d_out, int out_size) {
    const float* x    = (const float*)d_in[0];
    const float* w    = (const float*)d_in[1];
    const float* bias = (const float*)d_in[2];
    const float* s    = (const float*)d_in[3];
    float* out = (float*)d_out;

    k_init<<<1, 256>>>();
    k_scan<<<1024, 256>>>((const float4*)s, NTOT / 4, 24);
    k_pick<<<1, 1>>>(24);
    k_scan<<<1024, 256>>>((const float4*)s, NTOT / 4, 16);
    k_pick<<<1, 1>>>(16);
    k_scan<<<1024, 256>>>((const float4*)s, NTOT / 4, 8);
    k_pick<<<1, 1>>>(8);
    k_scan4<<<1024, 256>>>((const float4*)s, NTOT / 4);
    k_final<<<1, 1024>>>(s);

    k_split_w<<<2048, 256>>>((const float4*)w, (const float4*)s, NTOT / 4);
    k_split_a<<<4096, 256>>>((const float4*)x, (M_DIM * K_DIM) / 4);

    cudaFuncSetAttribute(k_gemm, cudaFuncAttributeMaxDynamicSharedMemorySize, SMEM_GEMM);
    k_gemm<<<GRID_P, 512, SMEM_GEMM>>>(bias, out);
}

// round 11
// speedup vs baseline: 8.6531x; 1.0749x over previous
#include <cuda_runtime.h>
#include <cuda_fp16.h>
#include <cstdint>

// ===========================================================================
// WeightPopupLayer: out = x @ (W * topk_mask(|scores|, 50%)).T + bias
// Round 11: single fp16-term persistent GEMM; per-slot empty-mbarriers
// replace the per-iteration __syncthreads (warps decoupled, jitter absorbed
// by the 4-deep ring). Split kernels: 8 elems/thread, single 16B store.
// ===========================================================================

#define NTOT    (4096 * 4096)
#define JRANK   8388608u
#define CMP_CAP (1 << 22)
#define TIE_CAP 4096

#define M_DIM 8192
#define N_DIM 4096
#define K_DIM 4096

#define WSCALE     16384.0f
#define INV_WSCALE (1.0f / 16384.0f)

// Blocked fp16 scratch:
//   g_ah: [by=32][ks=128] blocks of 256 rows x 64B = 16384 B
//   g_bh: [bx=32][ks=128] blocks of 128 rows x 64B =  8192 B
// In-block: off = rl*64 + ((cs ^ ((rl>>1)&3)) << 4) + (kl&7)*2
__device__ __align__(16) __half g_ah[M_DIM * K_DIM];   // 64 MB
__device__ __align__(16) __half g_bh[N_DIM * K_DIM];   // 32 MB

__device__ unsigned g_hist[256];
__device__ unsigned g_prefix;
__device__ unsigned g_rank;
__device__ unsigned g_ncomp;
__device__ unsigned g_idxcut;
__device__ unsigned g_cmp_val[CMP_CAP];
__device__ unsigned g_cmp_idx[CMP_CAP];

static __device__ __forceinline__ unsigned abs_bits(float v) {
    return __float_as_uint(fabsf(v));
}

// ======================= selection kernels =================================
__global__ void k_init() {
    int t = threadIdx.x;
    if (t < 256) g_hist[t] = 0;
    if (t == 0) { g_prefix = 0u; g_rank = JRANK; g_ncomp = 0u; g_idxcut = 0u; }
}

// simple histogram scan, 2x float4 unrolled
__global__ void k_scan(const float4* __restrict__ s4, int n4, int shift) {
    __shared__ unsigned sh[256];
    if (threadIdx.x < 256) sh[threadIdx.x] = 0;
    __syncthreads();
    const unsigned pref = g_prefix;
    const unsigned mask = (shift == 24) ? 0u : (0xFFFFFFFFu << (shift + 8));
    int stride = blockDim.x * gridDim.x;
    for (int i = blockIdx.x * blockDim.x + threadIdx.x; i < n4; i += 2 * stride) {
        float4 v1 = s4[i];
        int j = i + stride;
        bool h2 = (j < n4);
        float4 v2 = h2 ? s4[j] : make_float4(0.f, 0.f, 0.f, 0.f);
        unsigned b;
        b = abs_bits(v1.x); if ((b & mask) == pref) atomicAdd(&sh[(b >> shift) & 255], 1u);
        b = abs_bits(v1.y); if ((b & mask) == pref) atomicAdd(&sh[(b >> shift) & 255], 1u);
        b = abs_bits(v1.z); if ((b & mask) == pref) atomicAdd(&sh[(b >> shift) & 255], 1u);
        b = abs_bits(v1.w); if ((b & mask) == pref) atomicAdd(&sh[(b >> shift) & 255], 1u);
        if (h2) {
            b = abs_bits(v2.x); if ((b & mask) == pref) atomicAdd(&sh[(b >> shift) & 255], 1u);
            b = abs_bits(v2.y); if ((b & mask) == pref) atomicAdd(&sh[(b >> shift) & 255], 1u);
            b = abs_bits(v2.z); if ((b & mask) == pref) atomicAdd(&sh[(b >> shift) & 255], 1u);
            b = abs_bits(v2.w); if ((b & mask) == pref) atomicAdd(&sh[(b >> shift) & 255], 1u);
        }
    }
    __syncthreads();
    if (threadIdx.x < 256 && sh[threadIdx.x])
        atomicAdd(&g_hist[threadIdx.x], sh[threadIdx.x]);
}

__global__ void k_pick(int shift) {
    unsigned r = g_rank, cum = 0;
    #pragma unroll 1
    for (int b = 0; b < 256; ++b) {
        unsigned c = g_hist[b];
        if (cum + c > r) { g_prefix |= ((unsigned)b) << shift; g_rank = r - cum; break; }
        cum += c;
    }
    for (int b = 0; b < 256; ++b) g_hist[b] = 0;
}

// pass 4: byte0 histogram of top-24 matches + warp-aggregated compaction
__global__ void k_scan4(const float4* __restrict__ s4, int n4) {
    __shared__ unsigned sh[256];
    if (threadIdx.x < 256) sh[threadIdx.x] = 0;
    __syncthreads();
    const unsigned pref = g_prefix;           // top 24 bits set, low byte 0
    const int lane = threadIdx.x & 31;
    int stride = blockDim.x * gridDim.x;
    for (int i = blockIdx.x * blockDim.x + threadIdx.x; i < n4; i += stride) {
        bool valid = (i < n4);
        float4 v = valid ? s4[i] : make_float4(0.f, 0.f, 0.f, 0.f);
        unsigned bb[4] = {abs_bits(v.x), abs_bits(v.y), abs_bits(v.z), abs_bits(v.w)};
        unsigned fi = (unsigned)i << 2;
        #pragma unroll
        for (int c = 0; c < 4; ++c) {
            bool match = valid && ((bb[c] & 0xFFFFFF00u) == pref);
            if (match) atomicAdd(&sh[bb[c] & 255u], 1u);
            unsigned mk = __ballot_sync(0xFFFFFFFFu, match);
            if (mk) {
                int leader = __ffs(mk) - 1;
                unsigned base = 0;
                if (lane == leader) base = atomicAdd(&g_ncomp, (unsigned)__popc(mk));
                base = __shfl_sync(0xFFFFFFFFu, base, leader);
                if (match) {
                    unsigned off = base + __popc(mk & ((1u << lane) - 1u));
                    if (off < CMP_CAP) { g_cmp_val[off] = bb[c]; g_cmp_idx[off] = fi + c; }
                }
            }
        }
    }
    __syncthreads();
    if (threadIdx.x < 256 && sh[threadIdx.x])
        atomicAdd(&g_hist[threadIdx.x], sh[threadIdx.x]);
}

// final: pick byte0 + tie gather + stable-argsort index cut (one block)
__global__ void k_final(const float* __restrict__ sfull) {
    __shared__ unsigned v[256], ps[256];
    __shared__ unsigned tie[TIE_CAP];
    __shared__ unsigned s_cnt;
    const int t = threadIdx.x;
    if (t == 0) s_cnt = 0;
    if (t < 256) { v[t] = g_hist[t]; ps[t] = v[t]; }
    __syncthreads();
    for (int off = 1; off < 256; off <<= 1) {
        unsigned add = 0;
        if (t < 256 && t >= off) add = ps[t - off];
        __syncthreads();
        if (t < 256) ps[t] += add;
        __syncthreads();
    }
    unsigned r = g_rank;
    __syncthreads();
    if (t < 256) {
        unsigned excl = ps[t] - v[t];
        if (r >= excl && r < ps[t]) { g_prefix |= (unsigned)t; g_rank = r - excl; }
    }
    __syncthreads();
    const unsigned tb = g_prefix;
    const unsigned d  = g_rank;
    const unsigned m  = g_ncomp;
    const bool ok = (m <= (unsigned)CMP_CAP);
    if (ok) {
        for (unsigned i = t; i < m; i += blockDim.x) {
            if (g_cmp_val[i] == tb) {
                unsigned p = atomicAdd(&s_cnt, 1u);
                if (p < TIE_CAP) tie[p] = g_cmp_idx[i];
            }
        }
    } else {   // overflow fallback: full scan (slow, correct)
        for (unsigned i = t; i < (unsigned)NTOT; i += blockDim.x) {
            if (abs_bits(sfull[i]) == tb) {
                unsigned p = atomicAdd(&s_cnt, 1u);
                if (p < TIE_CAP) tie[p] = i;
            }
        }
    }
    __syncthreads();
    unsigned mm = min(s_cnt, (unsigned)TIE_CAP);
    if (t == 0) {
        if (d == 0u) g_idxcut = 0u;
        else if (d >= mm) g_idxcut = 0xFFFFFFFFu;
    }
    if (!(d == 0u || d >= mm)) {
        for (unsigned e = t; e < mm; e += blockDim.x) {
            unsigned vv = tie[e];
            unsigned rank = 0;
            for (unsigned f = 0; f < mm; ++f) rank += (tie[f] < vv);
            if (rank == d) g_idxcut = vv;
        }
    }
}

// ======================= split kernels (8 elems/thread) ====================
// masked W * 2^14 -> fp16 (blocked layout); one 16B store per thread-iter
__global__ void k_split_w(const float4* __restrict__ w4, const float4* __restrict__ s4, int n8) {
    const unsigned tb  = g_prefix;
    const unsigned cut = g_idxcut;
    int stride = blockDim.x * gridDim.x;
    for (int i = blockIdx.x * blockDim.x + threadIdx.x; i < n8; i += stride) {
        float4 wv0 = w4[2 * i], wv1 = w4[2 * i + 1];
        float4 sv0 = s4[2 * i], sv1 = s4[2 * i + 1];
        unsigned fi = (unsigned)i << 3;
        float fw[8] = {wv0.x, wv0.y, wv0.z, wv0.w, wv1.x, wv1.y, wv1.z, wv1.w};
        float fs[8] = {sv0.x, sv0.y, sv0.z, sv0.w, sv1.x, sv1.y, sv1.z, sv1.w};
        unsigned short h[8];
        #pragma unroll
        for (int c = 0; c < 8; ++c) {
            unsigned b = abs_bits(fs[c]);
            float f = (b > tb || (b == tb && fi + c >= cut)) ? fw[c] : 0.0f;
            h[c] = __half_as_ushort(__float2half_rn(f * WSCALE));
        }
        uint4 ph;
        ph.x = (unsigned)h[0] | ((unsigned)h[1] << 16);
        ph.y = (unsigned)h[2] | ((unsigned)h[3] << 16);
        ph.z = (unsigned)h[4] | ((unsigned)h[5] << 16);
        ph.w = (unsigned)h[6] | ((unsigned)h[7] << 16);
        unsigned row = fi >> 12, k = fi & 4095;
        unsigned bx = row >> 7, rl = row & 127;
        unsigned ks = k >> 5;
        unsigned cs = (k >> 3) & 3;              // (k&7)==0 here
        size_t   blk = (size_t)(bx * 128 + ks) << 13;
        unsigned off = rl * 64 + ((cs ^ ((rl >> 1) & 3)) << 4);
        *(uint4*)((char*)g_bh + blk + off) = ph;
    }
}

// x -> fp16 (blocked layout); one 16B store per thread-iter
__global__ void k_split_a(const float4* __restrict__ x4, int n8) {
    int stride = blockDim.x * gridDim.x;
    for (int i = blockIdx.x * blockDim.x + threadIdx.x; i < n8; i += stride) {
        float4 v0 = x4[2 * i], v1 = x4[2 * i + 1];
        float f[8] = {v0.x, v0.y, v0.z, v0.w, v1.x, v1.y, v1.z, v1.w};
        unsigned short h[8];
        #pragma unroll
        for (int c = 0; c < 8; ++c)
            h[c] = __half_as_ushort(__float2half_rn(f[c]));
        uint4 ph;
        ph.x = (unsigned)h[0] | ((unsigned)h[1] << 16);
        ph.y = (unsigned)h[2] | ((unsigned)h[3] << 16);
        ph.z = (unsigned)h[4] | ((unsigned)h[5] << 16);
        ph.w = (unsigned)h[6] | ((unsigned)h[7] << 16);
        unsigned fi = (unsigned)i << 3;
        unsigned row = fi >> 12, k = fi & 4095;
        unsigned by = row >> 8, rl = row & 255;
        unsigned ks = k >> 5;
        unsigned cs = (k >> 3) & 3;
        size_t   blk = (size_t)(by * 128 + ks) << 14;
        unsigned off = rl * 64 + ((cs ^ ((rl >> 1) & 3)) << 4);
        *(uint4*)((char*)g_ah + blk + off) = ph;
    }
}

// ======================= persistent GEMM ===================================
// 148 persistent CTAs, 512 threads = 16 warps (4x4), warp 64x32, tile
// 256x128. 4-stage x 48 KB bulk-DMA ring. Slot reuse guarded by per-slot
// "empty" mbarriers (16 warp-arrivals) instead of block-wide syncthreads.

#define GRID_P      148
#define N_TILES     1024
#define STAGES      4
#define STAGE_BYTES 49152
#define SM_AH       0
#define SM_BH       32768
#define SMEM_GEMM   (STAGES * STAGE_BYTES)    // 196608
#define TSTEPS      64                        // 64-K stages per tile

#define LDSM4(r0, r1, r2, r3, addr) \
    asm volatile("ldmatrix.sync.aligned.m8n8.x4.shared.b16 {%0,%1,%2,%3}, [%4];" \
                 : "=r"(r0), "=r"(r1), "=r"(r2), "=r"(r3) : "r"(addr))

#define MMA_F16(d, a0, a1, a2, a3, b0, b1) \
    asm volatile("mma.sync.aligned.m16n8k16.row.col.f32.f16.f16.f32 " \
                 "{%0,%1,%2,%3}, {%4,%5,%6,%7}, {%8,%9}, {%0,%1,%2,%3};" \
                 : "+f"((d)[0]), "+f"((d)[1]), "+f"((d)[2]), "+f"((d)[3]) \
                 : "r"(a0), "r"(a1), "r"(a2), "r"(a3), "r"(b0), "r"(b1))

#define MBARRIER_INIT(mbar, cnt) \
    asm volatile("mbarrier.init.shared.b64 [%0], %1;" :: "r"((uint32_t)(mbar)), "r"((uint32_t)(cnt)) : "memory")
#define MBARRIER_EXPECT_TX(mbar, tx) \
    asm volatile("mbarrier.arrive.expect_tx.shared.b64 _, [%0], %1;" :: "r"((uint32_t)(mbar)), "r"((uint32_t)(tx)) : "memory")
#define MBARRIER_ARRIVE(mbar) \
    asm volatile("mbarrier.arrive.release.cta.shared::cta.b64 _, [%0];" :: "r"((uint32_t)(mbar)) : "memory")

#define MBARRIER_WAIT_PARITY(mbar_smem_addr, phase_parity) do { \
    uint32_t _mbar = (uint32_t)(mbar_smem_addr); \
    uint32_t _parity = (uint32_t)(phase_parity); \
    uint32_t _done; \
    asm volatile("{\n\t.reg .pred p;\n\t" \
        "mbarrier.try_wait.parity.acquire.cta.shared::cta.b64 p, [%1], %2;\n\t" \
        "selp.b32 %0, 1, 0, p;\n\t}" \
        : "=r"(_done) : "r"(_mbar), "r"(_parity) : "memory"); \
    if (!_done) { \
        asm volatile("{\n\t.reg .pred P1;\n\t" \
            "WAIT_LOOP_%=:\n\t" \
            "mbarrier.try_wait.parity.acquire.cta.shared::cta.b64 P1, [%0], %1, 0x989680;\n\t" \
            "@P1 bra.uni WAIT_DONE_%=;\n\t" \
            "bra.uni WAIT_LOOP_%=;\n\t" \
            "WAIT_DONE_%=:\n\t}" \
            :: "r"(_mbar), "r"(_parity) : "memory"); \
    } \
} while (0)

static __device__ __forceinline__ void bulk_g2s(uint32_t dst, const void* src,
                                                uint32_t bytes, uint32_t mbar) {
    asm volatile(
        "cp.async.bulk.shared::cluster.global.mbarrier::complete_tx::bytes [%0], [%1], %2, [%3];"
        :: "r"(dst), "l"(src), "r"(bytes), "r"(mbar) : "memory");
}

// tile id -> (by, bx) raster
static __device__ __forceinline__ void tile_coords(int tau, int& by, int& bx) {
    by = (tau >> 8) * 8 + (tau & 7);
    bx = (tau >> 3) & 31;
}

static __device__ __forceinline__ void issue_stage(uint32_t sb, uint32_t mb,
                                                   int p, int g) {
    int tn = g >> 6, sn = g & 63;
    int tau = p + tn * GRID_P;
    int byn, bxn;
    tile_coords(tau, byn, bxn);
    const char* pa = (const char*)g_ah + ((size_t)byn * 128 << 14) + ((size_t)sn << 15);
    const char* pb = (const char*)g_bh + ((size_t)bxn * 128 << 13) + ((size_t)sn << 14);
    uint32_t mbar = mb + (uint32_t)(g & (STAGES - 1)) * 8;
    uint32_t dst  = sb + (uint32_t)(g & (STAGES - 1)) * STAGE_BYTES;
    MBARRIER_EXPECT_TX(mbar, STAGE_BYTES);
    bulk_g2s(dst + SM_AH, pa, 32768, mbar);
    bulk_g2s(dst + SM_BH, pb, 16384, mbar);
}

__global__ void __launch_bounds__(512, 1)
k_gemm(const float* __restrict__ bias, float* __restrict__ outp) {
    extern __shared__ __align__(16) char dsmem[];
    __shared__ __align__(8) unsigned long long s_mbar[2 * STAGES];  // full[4], empty[4]

    uint32_t sb, mb;
    asm("{ .reg .u64 t; cvta.to.shared.u64 t, %1; cvt.u32.u64 %0, t; }" : "=r"(sb) : "l"(dsmem));
    asm("{ .reg .u64 t; cvta.to.shared.u64 t, %1; cvt.u32.u64 %0, t; }" : "=r"(mb) : "l"(&s_mbar[0]));
    const uint32_t mbE = mb + STAGES * 8;

    const int tid  = threadIdx.x;
    const int wid  = tid >> 5;
    const int lane = tid & 31;
    const int p    = blockIdx.x;

    const int n_t  = (N_TILES - 1 - p) / GRID_P + 1;   // 6 or 7 tiles
    const int Gtot = n_t * TSTEPS;

    const int wm = wid >> 2;                 // 0..3
    const int wn = wid & 3;                  // 0..3

    uint32_t rowOffA[4], swzA[4];
    const uint32_t hiA = (lane >> 4) & 1;
    {
        int arow = wm * 64 + (lane & 15);
        #pragma unroll
        for (int mt = 0; mt < 4; ++mt) {
            int r = arow + mt * 16;
            rowOffA[mt] = (uint32_t)r * 64;
            swzA[mt]    = ((uint32_t)r >> 1) & 3;
        }
    }
    uint32_t rowOffB[2], swzB[2];
    const uint32_t hiB = (lane >> 3) & 1;
    {
        int brow_lo = ((lane >> 4) << 3) + (lane & 7);
        #pragma unroll
        for (int pp = 0; pp < 2; ++pp) {
            int r = wn * 32 + pp * 16 + brow_lo;
            rowOffB[pp] = (uint32_t)r * 64;
            swzB[pp]    = ((uint32_t)r >> 1) & 3;
        }
    }

    if (tid == 0) {
        #pragma unroll
        for (int s = 0; s < STAGES; ++s) {
            MBARRIER_INIT(mb + s * 8, 1);     // full: tx-based
            MBARRIER_INIT(mbE + s * 8, 16);   // empty: one arrive per warp
        }
    }
    __syncthreads();

    if (tid == 0) {
        #pragma unroll
        for (int g0 = 0; g0 < STAGES - 1; ++g0) issue_stage(sb, mb, p, g0);
    }

    int g = 0;
    #pragma unroll 1
    for (int t_idx = 0; t_idx < n_t; ++t_idx) {
        int tau = p + t_idx * GRID_P;
        int by, bx;
        tile_coords(tau, by, bx);

        float acc[4][4][4];
        #pragma unroll
        for (int i = 0; i < 4; ++i)
            #pragma unroll
            for (int j = 0; j < 4; ++j)
                #pragma unroll
                for (int e = 0; e < 4; ++e) acc[i][j][e] = 0.0f;

        #pragma unroll 1
        for (int s = 0; s < TSTEPS; ++s, ++g) {
            const int slot = g & (STAGES - 1);
            MBARRIER_WAIT_PARITY(mb + slot * 8, (g >> 2) & 1);

            uint32_t sbase = sb + (uint32_t)slot * STAGE_BYTES;
            #pragma unroll
            for (int half = 0; half < 2; ++half) {
                uint32_t abase = sbase + SM_AH + (uint32_t)half * 16384;
                uint32_t bbase = sbase + SM_BH + (uint32_t)half * 8192;
                #pragma unroll
                for (int ks = 0; ks < 2; ++ks) {
                    const uint32_t ks2 = (uint32_t)ks << 1;
                    uint32_t ah[4][4];
                    #pragma unroll
                    for (int mt = 0; mt < 4; ++mt) {
                        uint32_t a = abase + rowOffA[mt] + (((ks2 | hiA) ^ swzA[mt]) << 4);
                        LDSM4(ah[mt][0], ah[mt][1], ah[mt][2], ah[mt][3], a);
                    }
                    #pragma unroll
                    for (int pp = 0; pp < 2; ++pp) {
                        uint32_t bh[4];
                        uint32_t b = bbase + rowOffB[pp] + (((ks2 | hiB) ^ swzB[pp]) << 4);
                        LDSM4(bh[0], bh[1], bh[2], bh[3], b);
                        #pragma unroll
                        for (int mt = 0; mt < 4; ++mt) {
                            MMA_F16(acc[mt][2 * pp],     ah[mt][0], ah[mt][1], ah[mt][2], ah[mt][3], bh[0], bh[1]);
                            MMA_F16(acc[mt][2 * pp + 1], ah[mt][0], ah[mt][1], ah[mt][2], ah[mt][3], bh[2], bh[3]);
                        }
                    }
                }
            }

            // warp done reading this slot (all its LDSM results consumed)
            if (lane == 0) MBARRIER_ARRIVE(mbE + slot * 8);

            // producer: refill slot (g+3) once its previous user (g-1) drained
            if (tid == 0) {
                int n = g + STAGES - 1;
                if (n < Gtot) {
                    if (n >= STAGES)
                        MBARRIER_WAIT_PARITY(mbE + (n & (STAGES - 1)) * 8, ((n >> 2) + 1) & 1);
                    issue_stage(sb, mb, p, n);
                }
            }
        }

        // ---- epilogue: undo W scale, add bias, store fp32 ----
        #pragma unroll
        for (int nt = 0; nt < 4; ++nt) {
            int col = bx * 128 + wn * 32 + nt * 8 + (lane & 3) * 2;
            float2 bv = *(const float2*)(bias + col);
            #pragma unroll
            for (int mt = 0; mt < 4; ++mt) {
                int r0 = by * 256 + wm * 64 + mt * 16 + (lane >> 2);
                float2 o0, o1;
                o0.x = fmaf(acc[mt][nt][0], INV_WSCALE, bv.x);
                o0.y = fmaf(acc[mt][nt][1], INV_WSCALE, bv.y);
                o1.x = fmaf(acc[mt][nt][2], INV_WSCALE, bv.x);
                o1.y = fmaf(acc[mt][nt][3], INV_WSCALE, bv.y);
                *(float2*)(outp + (size_t)r0 * N_DIM + col)       = o0;
                *(float2*)(outp + (size_t)(r0 + 8) * N_DIM + col) = o1;
            }
        }
    }
}

// ===========================================================================
extern "C" void kernel_launch(void* const* d_in, const int* in_sizes, int n_in,
                              void* d_out, int out_size) {
    const float* x    = (const float*)d_in[0];
    const float* w    = (const float*)d_in[1];
    const float* bias = (const float*)d_in[2];
    const float* s    = (const float*)d_in[3];
    float* out = (float*)d_out;

    k_init<<<1, 256>>>();
    k_scan<<<1024, 256>>>((const float4*)s, NTOT / 4, 24);
    k_pick<<<1, 1>>>(24);
    k_scan<<<1024, 256>>>((const float4*)s, NTOT / 4, 16);
    k_pick<<<1, 1>>>(16);
    k_scan<<<1024, 256>>>((const float4*)s, NTOT / 4, 8);
    k_pick<<<1, 1>>>(8);
    k_scan4<<<1024, 256>>>((const float4*)s, NTOT / 4);
    k_final<<<1, 1024>>>(s);

    k_split_w<<<2048, 256>>>((const float4*)w, (const float4*)s, NTOT / 8);
    k_split_a<<<4096, 256>>>((const float4*)x, (M_DIM * K_DIM) / 8);

    cudaFuncSetAttribute(k_gemm, cudaFuncAttributeMaxDynamicSharedMemorySize, SMEM_GEMM);
    k_gemm<<<GRID_P, 512, SMEM_GEMM>>>(bias, out);
}